// round 8
// baseline (speedup 1.0000x reference)
#include <cuda_runtime.h>
#include <cuda_fp16.h>
#include <cstdint>

#define DIM   2048
#define NHEAD 16
#define HDIM  128
#define BATCH 2
#define SEQ   2048
#define MROWS (BATCH*SEQ)   // 4096

// ---- fp16 GEMM tile config ----
#define GBM 128
#define GBN 128
#define GBK 64                         // 64 halfs = 128 bytes = one swizzle row
#define GSTAGES 3
#define STAGE_T_BYTES (128 * 128)      // one operand tile per stage: 16384 B
#define GSMEM_BYTES (GSTAGES * 2 * STAGE_T_BYTES)   // 98304
#define GTHREADS 256

#define SW128(o) ((o) ^ ((((uint32_t)(o)) >> 3) & 0x70u))

// log2(10000)/64 : inv_freq(j) = 2^(-j * ROPE_C) = 10000^(-2j/128)
#define ROPE_C 0.20762050593046014f

// Scratch (allocation-free rule: __device__ globals)
__device__ __half g_q[(size_t)MROWS * DIM];
__device__ __half g_k[(size_t)MROWS * DIM];
__device__ __half g_v[(size_t)MROWS * DIM];
__device__ __half g_attn[(size_t)MROWS * DIM];
__device__ __half g_xr[(size_t)MROWS * DIM];
__device__ __half g_wqr[(size_t)DIM * DIM];
__device__ __half g_wkr[(size_t)DIM * DIM];
__device__ __half g_wvr[(size_t)DIM * DIM];
__device__ __half g_wor[(size_t)DIM * DIM];

// ---------------------------------------------------------------------------
// PTX helpers
// ---------------------------------------------------------------------------
__device__ __forceinline__ void mma_f16(float c[4], const uint32_t a[4], const uint32_t b[2]) {
    asm volatile(
        "mma.sync.aligned.m16n8k16.row.col.f32.f16.f16.f32 "
        "{%0,%1,%2,%3}, {%4,%5,%6,%7}, {%8,%9}, {%0,%1,%2,%3};\n"
        : "+f"(c[0]), "+f"(c[1]), "+f"(c[2]), "+f"(c[3])
        : "r"(a[0]), "r"(a[1]), "r"(a[2]), "r"(a[3]), "r"(b[0]), "r"(b[1]));
}

#define LDSM_X4(r0, r1, r2, r3, addr)                                       \
    asm volatile("ldmatrix.sync.aligned.m8n8.x4.shared.b16 {%0,%1,%2,%3}, [%4];" \
                 : "=r"(r0), "=r"(r1), "=r"(r2), "=r"(r3) : "r"(addr))

#define LDSM_X4_T(r0, r1, r2, r3, addr)                                     \
    asm volatile("ldmatrix.sync.aligned.m8n8.x4.trans.shared.b16 {%0,%1,%2,%3}, [%4];" \
                 : "=r"(r0), "=r"(r1), "=r"(r2), "=r"(r3) : "r"(addr))

__device__ __forceinline__ void cp16(void* dst, const void* src) {
    uint32_t s = (uint32_t)__cvta_generic_to_shared(dst);
    asm volatile("cp.async.cg.shared.global [%0], [%1], 16;" :: "r"(s), "l"(src));
}

__device__ __forceinline__ uint32_t smem_u32(const void* p) {
    return (uint32_t)__cvta_generic_to_shared(p);
}

__device__ __forceinline__ uint32_t packh2(float a, float b) {
    __half2 h = __floats2half2_rn(a, b);
    return *(uint32_t*)&h;
}

__device__ __forceinline__ void store_pair(__half* p, float a, float b) {
    *(uint32_t*)p = packh2(a, b);
}
__device__ __forceinline__ void store_pair(float* p, float a, float b) {
    *(float2*)p = make_float2(a, b);
}

// ---------------------------------------------------------------------------
// Fused f32 -> f16 conversion: grid.z selects tensor (0=x, 1..4=weights)
// ---------------------------------------------------------------------------
__global__ void convert_all_kernel(const float* __restrict__ x,
                                   const float* __restrict__ wq, const float* __restrict__ wk,
                                   const float* __restrict__ wv, const float* __restrict__ wo,
                                   __half* __restrict__ xr,
                                   __half* __restrict__ wqr, __half* __restrict__ wkr,
                                   __half* __restrict__ wvr, __half* __restrict__ wor) {
    const int z = blockIdx.z;
    const int nw4 = DIM * DIM / 4;
    if (z > 0 && blockIdx.x >= (unsigned)(nw4 / 256)) return;
    int t = blockIdx.x * 256 + threadIdx.x;
    const float* in;
    __half* out;
    switch (z) {
        case 0: in = x;  out = xr;  break;
        case 1: in = wq; out = wqr; break;
        case 2: in = wk; out = wkr; break;
        case 3: in = wv; out = wvr; break;
        default: in = wo; out = wor; break;
    }
    float4 v = ((const float4*)in)[t];
    ((uint2*)out)[t] = make_uint2(packh2(v.x, v.y), packh2(v.z, v.w));
}

// ---------------------------------------------------------------------------
// fp16 TN GEMM: C[m,n] = sum_k A[m,k]*B[n,k], f32 accumulate.
// CTA 128x128, BK=64 halfs, 8 warps (warp tile 64x32), 3-stage cp.async,
// SW128-swizzled smem, ldmatrix fragment loads.
// do_rope (half output only): N-tile == one head; stage f32 accs in smem,
// apply non-interleaved RoPE, store fp16 once.
// ---------------------------------------------------------------------------
template <typename OutT>
__device__ __forceinline__ void gemm_fp16_body(const __half* __restrict__ A,
                                               const __half* __restrict__ B,
                                               OutT* __restrict__ C,
                                               char* smem, bool do_rope) {
    const int K = DIM, N = DIM;
    const int tid = threadIdx.x;
    const int warp = tid >> 5, lane = tid & 31;
    const int m0 = blockIdx.y * GBM, n0 = blockIdx.x * GBN;
    const int wm = warp >> 2, wn = warp & 3;      // 2x4 warps -> warp tile 64x32
    const int r = lane >> 2, cq = lane & 3;

    char* As = smem;
    char* Bs = smem + GSTAGES * STAGE_T_BYTES;
    const uint32_t uA = smem_u32(As);
    const uint32_t uB = smem_u32(Bs);

    float acc[4][4][4];
#pragma unroll
    for (int mt = 0; mt < 4; mt++)
#pragma unroll
        for (int nf = 0; nf < 4; nf++)
#pragma unroll
            for (int q = 0; q < 4; q++) acc[mt][nf][q] = 0.f;

#define G_LOAD_STAGE(slot, kt)                                                     \
    do {                                                                           \
        const __half* Ag = A + (size_t)m0 * K + (size_t)(kt) * GBK;                \
        const __half* Bg = B + (size_t)n0 * K + (size_t)(kt) * GBK;                \
        _Pragma("unroll")                                                          \
        for (int i = 0; i < 4; i++) {                                              \
            int c = tid + i * GTHREADS;                                            \
            int row = c >> 3, ch = c & 7;                                          \
            uint32_t sw = SW128((uint32_t)(row * 128 + ch * 16));                  \
            cp16(As + (slot) * STAGE_T_BYTES + sw, Ag + (size_t)row * K + ch * 8); \
            cp16(Bs + (slot) * STAGE_T_BYTES + sw, Bg + (size_t)row * K + ch * 8); \
        }                                                                          \
    } while (0)

    G_LOAD_STAGE(0, 0);
    asm volatile("cp.async.commit_group;");
    G_LOAD_STAGE(1, 1);
    asm volatile("cp.async.commit_group;");

    const int KT = K / GBK;  // 32
    for (int kt = 0; kt < KT; kt++) {
        asm volatile("cp.async.wait_group 1;");
        __syncthreads();
        int pf = kt + GSTAGES - 1;
        if (pf < KT) G_LOAD_STAGE(pf % GSTAGES, pf);
        asm volatile("cp.async.commit_group;");

        const uint32_t aBase = uA + (kt % GSTAGES) * STAGE_T_BYTES;
        const uint32_t bBase = uB + (kt % GSTAGES) * STAGE_T_BYTES;

#pragma unroll
        for (int kk = 0; kk < 4; kk++) {          // 4 x k16 per stage
            const int c0 = kk * 2;
            uint32_t af[4][4], bf[4][2];
#pragma unroll
            for (int mt = 0; mt < 4; mt++) {
                int row = wm * 64 + mt * 16 + (lane & 15);
                int ch = c0 + (lane >> 4);
                uint32_t addr = aBase + SW128((uint32_t)(row * 128 + ch * 16));
                LDSM_X4(af[mt][0], af[mt][1], af[mt][2], af[mt][3], addr);
            }
#pragma unroll
            for (int g = 0; g < 2; g++) {
                int row = wn * 32 + g * 16 + (lane & 7) + ((lane >> 4) << 3);
                int ch = c0 + ((lane >> 3) & 1);
                uint32_t addr = bBase + SW128((uint32_t)(row * 128 + ch * 16));
                LDSM_X4(bf[2 * g][0], bf[2 * g][1], bf[2 * g + 1][0], bf[2 * g + 1][1], addr);
            }
#pragma unroll
            for (int mt = 0; mt < 4; mt++)
#pragma unroll
                for (int nf = 0; nf < 4; nf++) mma_f16(acc[mt][nf], af[mt], bf[nf]);
        }
        __syncthreads();
    }
#undef G_LOAD_STAGE

    if (sizeof(OutT) == 2 && do_rope) {
        // --- fused RoPE epilogue: stage f32 accs in (now free) stage smem ---
        asm volatile("cp.async.wait_group 0;");
        __syncthreads();
        float* Ts = (float*)smem;               // [128][132]
#pragma unroll
        for (int mt = 0; mt < 4; mt++) {
            int row0 = wm * 64 + mt * 16 + r;
#pragma unroll
            for (int nf = 0; nf < 4; nf++) {
                int col = wn * 32 + nf * 8 + 2 * cq;
                *(float2*)&Ts[row0 * 132 + col] = make_float2(acc[mt][nf][0], acc[mt][nf][1]);
                *(float2*)&Ts[(row0 + 8) * 132 + col] = make_float2(acc[mt][nf][2], acc[mt][nf][3]);
            }
        }
        __syncthreads();

        const int r2 = tid >> 1;                // 0..127  (tile row)
        const int j0 = (tid & 1) * 32;          // 0 or 32
        const float sf = (float)((m0 + r2) & (SEQ - 1));
        __half* Crow = (__half*)C + (size_t)(m0 + r2) * N + n0;
        const float* Trow = Ts + r2 * 132;
#pragma unroll
        for (int j = j0; j < j0 + 32; j += 2) {
            float if0 = exp2f(-(float)j * ROPE_C);
            float if1 = exp2f(-(float)(j + 1) * ROPE_C);
            float sn0, cs0, sn1, cs1;
            sincosf(sf * if0, &sn0, &cs0);
            sincosf(sf * if1, &sn1, &cs1);
            float x1a = Trow[j], x1b = Trow[j + 1];
            float x2a = Trow[j + 64], x2b = Trow[j + 65];
            store_pair(Crow + j, x1a * cs0 - x2a * sn0, x1b * cs1 - x2b * sn1);
            store_pair(Crow + j + 64, x1a * sn0 + x2a * cs0, x1b * sn1 + x2b * cs1);
        }
    } else {
#pragma unroll
        for (int mt = 0; mt < 4; mt++) {
            int row0 = m0 + wm * 64 + mt * 16 + r;
#pragma unroll
            for (int nf = 0; nf < 4; nf++) {
                int col = n0 + wn * 32 + nf * 8 + 2 * cq;
                store_pair(C + (size_t)row0 * N + col, acc[mt][nf][0], acc[mt][nf][1]);
                store_pair(C + (size_t)(row0 + 8) * N + col, acc[mt][nf][2], acc[mt][nf][3]);
            }
        }
    }
}

__global__ __launch_bounds__(GTHREADS, 2) void gemm_qkv_kernel(
    const __half* __restrict__ x,
    const __half* __restrict__ wq, const __half* __restrict__ wk, const __half* __restrict__ wv,
    __half* __restrict__ q, __half* __restrict__ k, __half* __restrict__ v) {
    extern __shared__ char smem[];
    const __half* B = (blockIdx.z == 0) ? wq : (blockIdx.z == 1) ? wk : wv;
    __half* C       = (blockIdx.z == 0) ? q  : (blockIdx.z == 1) ? k  : v;
    gemm_fp16_body<__half>(x, B, C, smem, blockIdx.z < 2);
}

__global__ __launch_bounds__(GTHREADS, 2) void gemm_out_kernel(const __half* __restrict__ A,
                                                               const __half* __restrict__ B,
                                                               float* __restrict__ C) {
    extern __shared__ char smem[];
    gemm_fp16_body<float>(A, B, C, smem, false);
}

// ---------------------------------------------------------------------------
// Causal flash attention, fp16 mma. Grid: (S/128, H, B), 256 threads
// (8 warps x 16 q-rows => 128-row Q tile, halved KV traffic). 32-key blocks.
// Q in registers; K via ldmatrix; V via ldmatrix.trans; P packed directly
// from S accumulators.
// ---------------------------------------------------------------------------
#define KPAD 136   // padded row stride in halfs (272 B) — conflict-free ldmatrix

__global__ __launch_bounds__(256) void flash_kernel(const __half* __restrict__ Q,
                                                    const __half* __restrict__ Kg,
                                                    const __half* __restrict__ Vg,
                                                    __half* __restrict__ O) {
    __shared__ __half Ks[32][KPAD];
    __shared__ __half Vs[32][KPAD];

    const int tid = threadIdx.x;
    const int warp = tid >> 5, lane = tid & 31;
    const int r = lane >> 2, cq = lane & 3;
    const int q0 = blockIdx.x * 128;
    const int h = blockIdx.y, b = blockIdx.z;
    const size_t head_off = (size_t)b * SEQ * DIM + (size_t)h * HDIM;
    const uint32_t uK = smem_u32(&Ks[0][0]);
    const uint32_t uV = smem_u32(&Vs[0][0]);

    // ---- Q fragments: 8 k16-chunks x 4 regs (16 rows per warp) ----
    const __half* Qp = Q + head_off + (size_t)(q0 + warp * 16) * DIM;
    uint32_t aQ[8][4];
#pragma unroll
    for (int kc = 0; kc < 8; kc++) {
        aQ[kc][0] = *(const uint32_t*)(Qp + (size_t)r * DIM + kc * 16 + 2 * cq);
        aQ[kc][1] = *(const uint32_t*)(Qp + (size_t)(r + 8) * DIM + kc * 16 + 2 * cq);
        aQ[kc][2] = *(const uint32_t*)(Qp + (size_t)r * DIM + kc * 16 + 8 + 2 * cq);
        aQ[kc][3] = *(const uint32_t*)(Qp + (size_t)(r + 8) * DIM + kc * 16 + 8 + 2 * cq);
    }

    float o[16][4];
#pragma unroll
    for (int i = 0; i < 16; i++)
#pragma unroll
        for (int j = 0; j < 4; j++) o[i][j] = 0.f;
    float m0 = -1e30f, m1 = -1e30f, l0 = 0.f, l1 = 0.f;

    const int nkb = (q0 >> 5) + 4;   // causal: keys up to q0+127
    for (int kb = 0; kb < nkb; kb++) {
        const int kstart = kb * 32;
        __syncthreads();

        // K,V tiles -> smem (uint4, coalesced; 512 chunks each, 2/thread)
        const __half* Kp = Kg + head_off + (size_t)kstart * DIM;
        const __half* Vp = Vg + head_off + (size_t)kstart * DIM;
#pragma unroll
        for (int i = 0; i < 2; i++) {
            int c = tid + i * 256;
            int row = c >> 4, ch = c & 15;
            *(uint4*)&Ks[row][ch * 8] = *(const uint4*)(Kp + (size_t)row * DIM + ch * 8);
            *(uint4*)&Vs[row][ch * 8] = *(const uint4*)(Vp + (size_t)row * DIM + ch * 8);
        }
        __syncthreads();

        // ---- S = Q K^T (16 rows x 32 keys per warp) ----
        float s[4][4];
#pragma unroll
        for (int nt = 0; nt < 4; nt++)
#pragma unroll
            for (int j = 0; j < 4; j++) s[nt][j] = 0.f;
#pragma unroll
        for (int kc = 0; kc < 8; kc++) {
            uint32_t bf[4][2];
#pragma unroll
            for (int g = 0; g < 2; g++) {
                int row = g * 16 + (lane & 7) + ((lane >> 4) << 3);
                int ch = kc * 2 + ((lane >> 3) & 1);
                uint32_t addr = uK + (uint32_t)(row * (KPAD * 2) + ch * 16);
                LDSM_X4(bf[2 * g][0], bf[2 * g][1], bf[2 * g + 1][0], bf[2 * g + 1][1], addr);
            }
#pragma unroll
            for (int nt = 0; nt < 4; nt++) mma_f16(s[nt], aQ[kc], bf[nt]);
        }

        const float scale = 0.08838834764831843f;  // 1/sqrt(128)
        const int qrow0 = q0 + warp * 16 + r;
        const bool need_mask = (kstart + 31 > q0 + warp * 16);
#pragma unroll
        for (int nt = 0; nt < 4; nt++) {
#pragma unroll
            for (int u = 0; u < 2; u++) {
                int key = kstart + nt * 8 + 2 * cq + u;
                s[nt][u] *= scale;
                s[nt][2 + u] *= scale;
                if (need_mask) {
                    if (key > qrow0) s[nt][u] = -1e30f;
                    if (key > qrow0 + 8) s[nt][2 + u] = -1e30f;
                }
            }
        }

        // ---- online softmax ----
        float mx0 = -1e30f, mx1 = -1e30f;
#pragma unroll
        for (int nt = 0; nt < 4; nt++) {
            mx0 = fmaxf(mx0, fmaxf(s[nt][0], s[nt][1]));
            mx1 = fmaxf(mx1, fmaxf(s[nt][2], s[nt][3]));
        }
        mx0 = fmaxf(mx0, __shfl_xor_sync(0xffffffffu, mx0, 1));
        mx0 = fmaxf(mx0, __shfl_xor_sync(0xffffffffu, mx0, 2));
        mx1 = fmaxf(mx1, __shfl_xor_sync(0xffffffffu, mx1, 1));
        mx1 = fmaxf(mx1, __shfl_xor_sync(0xffffffffu, mx1, 2));
        float mn0 = fmaxf(m0, mx0), mn1 = fmaxf(m1, mx1);
        float al0 = __expf(m0 - mn0), al1 = __expf(m1 - mn1);
        float sum0 = 0.f, sum1 = 0.f;
#pragma unroll
        for (int nt = 0; nt < 4; nt++) {
            s[nt][0] = __expf(s[nt][0] - mn0);
            s[nt][1] = __expf(s[nt][1] - mn0);
            s[nt][2] = __expf(s[nt][2] - mn1);
            s[nt][3] = __expf(s[nt][3] - mn1);
            sum0 += s[nt][0] + s[nt][1];
            sum1 += s[nt][2] + s[nt][3];
        }
        sum0 += __shfl_xor_sync(0xffffffffu, sum0, 1);
        sum0 += __shfl_xor_sync(0xffffffffu, sum0, 2);
        sum1 += __shfl_xor_sync(0xffffffffu, sum1, 1);
        sum1 += __shfl_xor_sync(0xffffffffu, sum1, 2);
        l0 = l0 * al0 + sum0;
        l1 = l1 * al1 + sum1;
        m0 = mn0;
        m1 = mn1;
#pragma unroll
        for (int nt = 0; nt < 16; nt++) {
            o[nt][0] *= al0;
            o[nt][1] *= al0;
            o[nt][2] *= al1;
            o[nt][3] *= al1;
        }

        // ---- O += P V : P fragments packed straight from S accumulators ----
#pragma unroll
        for (int g = 0; g < 2; g++) {
            uint32_t aP[4];
            aP[0] = packh2(s[2 * g][0], s[2 * g][1]);
            aP[1] = packh2(s[2 * g][2], s[2 * g][3]);
            aP[2] = packh2(s[2 * g + 1][0], s[2 * g + 1][1]);
            aP[3] = packh2(s[2 * g + 1][2], s[2 * g + 1][3]);
#pragma unroll
            for (int p = 0; p < 8; p++) {   // pairs of d-tiles
                uint32_t bv[2][2];
                int row = g * 16 + (lane & 7) + (((lane >> 3) & 1) << 3);
                int ch = 2 * p + (lane >> 4);
                uint32_t addr = uV + (uint32_t)(row * (KPAD * 2) + ch * 16);
                LDSM_X4_T(bv[0][0], bv[0][1], bv[1][0], bv[1][1], addr);
                mma_f16(o[2 * p], aP, bv[0]);
                mma_f16(o[2 * p + 1], aP, bv[1]);
            }
        }
    }

    const float inv0 = 1.f / l0, inv1 = 1.f / l1;
    __half* Op = O + head_off + (size_t)(q0 + warp * 16) * DIM;
#pragma unroll
    for (int nt = 0; nt < 16; nt++) {
        int col = nt * 8 + 2 * cq;
        store_pair(Op + (size_t)r * DIM + col, o[nt][0] * inv0, o[nt][1] * inv0);
        store_pair(Op + (size_t)(r + 8) * DIM + col, o[nt][2] * inv1, o[nt][3] * inv1);
    }
}

// ---------------------------------------------------------------------------
extern "C" void kernel_launch(void* const* d_in, const int* in_sizes, int n_in,
                              void* d_out, int out_size) {
    const float* x  = (const float*)d_in[0];
    const float* Wq = (const float*)d_in[1];
    const float* Wk = (const float*)d_in[2];
    const float* Wv = (const float*)d_in[3];
    const float* Wo = (const float*)d_in[4];
    float* out = (float*)d_out;

    __half *qp, *kp, *vp, *ap, *xr, *wqr, *wkr, *wvr, *wor;
    cudaGetSymbolAddress((void**)&qp, g_q);
    cudaGetSymbolAddress((void**)&kp, g_k);
    cudaGetSymbolAddress((void**)&vp, g_v);
    cudaGetSymbolAddress((void**)&ap, g_attn);
    cudaGetSymbolAddress((void**)&xr, g_xr);
    cudaGetSymbolAddress((void**)&wqr, g_wqr);
    cudaGetSymbolAddress((void**)&wkr, g_wkr);
    cudaGetSymbolAddress((void**)&wvr, g_wvr);
    cudaGetSymbolAddress((void**)&wor, g_wor);

    cudaFuncSetAttribute(gemm_qkv_kernel, cudaFuncAttributeMaxDynamicSharedMemorySize, GSMEM_BYTES);
    cudaFuncSetAttribute(gemm_out_kernel, cudaFuncAttributeMaxDynamicSharedMemorySize, GSMEM_BYTES);

    // One fused conversion launch: z=0 covers x (8192 blocks), z=1..4 weights (4096)
    convert_all_kernel<<<dim3(MROWS * DIM / 4 / 256, 1, 5), 256>>>(
        x, Wq, Wk, Wv, Wo, xr, wqr, wkr, wvr, wor);

    dim3 gqkv(DIM / GBN, MROWS / GBM, 3);  // (16, 32, 3) — rope fused for z<2
    gemm_qkv_kernel<<<gqkv, GTHREADS, GSMEM_BYTES>>>(xr, wqr, wkr, wvr, qp, kp, vp);

    flash_kernel<<<dim3(SEQ / 128, NHEAD, BATCH), 256>>>(qp, kp, vp, ap);

    gemm_out_kernel<<<dim3(DIM / GBN, MROWS / GBM), GTHREADS, GSMEM_BYTES>>>(ap, wor, out);
}

// round 9
// speedup vs baseline: 1.1328x; 1.1328x over previous
#include <cuda_runtime.h>
#include <cuda_fp16.h>
#include <cstdint>

#define DIM   2048
#define NHEAD 16
#define HDIM  128
#define BATCH 2
#define SEQ   2048
#define MROWS (BATCH*SEQ)   // 4096

// ---- fp16 GEMM tile config ----
#define GBM 128
#define GBN 128
#define GBK 64                         // 64 halfs = 128 bytes = one swizzle row
#define GSTAGES 3
#define STAGE_T_BYTES (128 * 128)      // one operand tile per stage: 16384 B
#define GSMEM_BYTES (GSTAGES * 2 * STAGE_T_BYTES)   // 98304
#define GTHREADS 256

#define SW128(o) ((o) ^ ((((uint32_t)(o)) >> 3) & 0x70u))

// Scratch (allocation-free rule: __device__ globals)
__device__ __half g_q[(size_t)MROWS * DIM];
__device__ __half g_k[(size_t)MROWS * DIM];
__device__ __half g_v[(size_t)MROWS * DIM];
__device__ __half g_attn[(size_t)MROWS * DIM];
__device__ __half g_xr[(size_t)MROWS * DIM];
__device__ __half g_wqr[(size_t)DIM * DIM];
__device__ __half g_wkr[(size_t)DIM * DIM];
__device__ __half g_wvr[(size_t)DIM * DIM];
__device__ __half g_wor[(size_t)DIM * DIM];

// ---------------------------------------------------------------------------
// PTX helpers
// ---------------------------------------------------------------------------
__device__ __forceinline__ void mma_f16(float c[4], const uint32_t a[4], const uint32_t b[2]) {
    asm volatile(
        "mma.sync.aligned.m16n8k16.row.col.f32.f16.f16.f32 "
        "{%0,%1,%2,%3}, {%4,%5,%6,%7}, {%8,%9}, {%0,%1,%2,%3};\n"
        : "+f"(c[0]), "+f"(c[1]), "+f"(c[2]), "+f"(c[3])
        : "r"(a[0]), "r"(a[1]), "r"(a[2]), "r"(a[3]), "r"(b[0]), "r"(b[1]));
}

#define LDSM_X4(r0, r1, r2, r3, addr)                                       \
    asm volatile("ldmatrix.sync.aligned.m8n8.x4.shared.b16 {%0,%1,%2,%3}, [%4];" \
                 : "=r"(r0), "=r"(r1), "=r"(r2), "=r"(r3) : "r"(addr))

#define LDSM_X4_T(r0, r1, r2, r3, addr)                                     \
    asm volatile("ldmatrix.sync.aligned.m8n8.x4.trans.shared.b16 {%0,%1,%2,%3}, [%4];" \
                 : "=r"(r0), "=r"(r1), "=r"(r2), "=r"(r3) : "r"(addr))

__device__ __forceinline__ void cp16(void* dst, const void* src) {
    uint32_t s = (uint32_t)__cvta_generic_to_shared(dst);
    asm volatile("cp.async.cg.shared.global [%0], [%1], 16;" :: "r"(s), "l"(src));
}

__device__ __forceinline__ uint32_t smem_u32(const void* p) {
    return (uint32_t)__cvta_generic_to_shared(p);
}

__device__ __forceinline__ uint32_t packh2(float a, float b) {
    __half2 h = __floats2half2_rn(a, b);
    return *(uint32_t*)&h;
}

__device__ __forceinline__ void store_pair(__half* p, float a, float b) {
    *(uint32_t*)p = packh2(a, b);
}
__device__ __forceinline__ void store_pair(float* p, float a, float b) {
    *(float2*)p = make_float2(a, b);
}

// ---------------------------------------------------------------------------
// Fused f32 -> f16 conversion: grid.z selects tensor (0=x, 1..4=weights)
// ---------------------------------------------------------------------------
__global__ void convert_all_kernel(const float* __restrict__ x,
                                   const float* __restrict__ wq, const float* __restrict__ wk,
                                   const float* __restrict__ wv, const float* __restrict__ wo,
                                   __half* __restrict__ xr,
                                   __half* __restrict__ wqr, __half* __restrict__ wkr,
                                   __half* __restrict__ wvr, __half* __restrict__ wor) {
    const int z = blockIdx.z;
    const int nw4 = DIM * DIM / 4;
    if (z > 0 && blockIdx.x >= (unsigned)(nw4 / 256)) return;
    int t = blockIdx.x * 256 + threadIdx.x;
    const float* in;
    __half* out;
    switch (z) {
        case 0: in = x;  out = xr;  break;
        case 1: in = wq; out = wqr; break;
        case 2: in = wk; out = wkr; break;
        case 3: in = wv; out = wvr; break;
        default: in = wo; out = wor; break;
    }
    float4 v = ((const float4*)in)[t];
    ((uint2*)out)[t] = make_uint2(packh2(v.x, v.y), packh2(v.z, v.w));
}

// ---------------------------------------------------------------------------
// fp16 TN GEMM: C[m,n] = sum_k A[m,k]*B[n,k], f32 accumulate.
// CTA 128x128, BK=64 halfs, 8 warps (warp tile 64x32), 3-stage cp.async,
// SW128-swizzled smem, ldmatrix fragment loads. ONE barrier per k-step:
// the top wait_group+syncthreads already orders compute(kt) before any
// thread can issue loads into stage (kt+3)%3 == kt%3.
// ---------------------------------------------------------------------------
template <typename OutT>
__device__ __forceinline__ void gemm_fp16_body(const __half* __restrict__ A,
                                               const __half* __restrict__ B,
                                               OutT* __restrict__ C,
                                               char* smem) {
    const int K = DIM, N = DIM;
    const int tid = threadIdx.x;
    const int warp = tid >> 5, lane = tid & 31;
    const int m0 = blockIdx.y * GBM, n0 = blockIdx.x * GBN;
    const int wm = warp >> 2, wn = warp & 3;      // 2x4 warps -> warp tile 64x32
    const int r = lane >> 2, cq = lane & 3;

    char* As = smem;
    char* Bs = smem + GSTAGES * STAGE_T_BYTES;
    const uint32_t uA = smem_u32(As);
    const uint32_t uB = smem_u32(Bs);

    float acc[4][4][4];
#pragma unroll
    for (int mt = 0; mt < 4; mt++)
#pragma unroll
        for (int nf = 0; nf < 4; nf++)
#pragma unroll
            for (int q = 0; q < 4; q++) acc[mt][nf][q] = 0.f;

#define G_LOAD_STAGE(slot, kt)                                                     \
    do {                                                                           \
        const __half* Ag = A + (size_t)m0 * K + (size_t)(kt) * GBK;                \
        const __half* Bg = B + (size_t)n0 * K + (size_t)(kt) * GBK;                \
        _Pragma("unroll")                                                          \
        for (int i = 0; i < 4; i++) {                                              \
            int c = tid + i * GTHREADS;                                            \
            int row = c >> 3, ch = c & 7;                                          \
            uint32_t sw = SW128((uint32_t)(row * 128 + ch * 16));                  \
            cp16(As + (slot) * STAGE_T_BYTES + sw, Ag + (size_t)row * K + ch * 8); \
            cp16(Bs + (slot) * STAGE_T_BYTES + sw, Bg + (size_t)row * K + ch * 8); \
        }                                                                          \
    } while (0)

    G_LOAD_STAGE(0, 0);
    asm volatile("cp.async.commit_group;");
    G_LOAD_STAGE(1, 1);
    asm volatile("cp.async.commit_group;");

    const int KT = K / GBK;  // 32
    for (int kt = 0; kt < KT; kt++) {
        asm volatile("cp.async.wait_group 1;");
        __syncthreads();
        int pf = kt + GSTAGES - 1;
        if (pf < KT) G_LOAD_STAGE(pf % GSTAGES, pf);
        asm volatile("cp.async.commit_group;");

        const uint32_t aBase = uA + (kt % GSTAGES) * STAGE_T_BYTES;
        const uint32_t bBase = uB + (kt % GSTAGES) * STAGE_T_BYTES;

#pragma unroll
        for (int kk = 0; kk < 4; kk++) {          // 4 x k16 per stage
            const int c0 = kk * 2;
            uint32_t af[4][4], bf[4][2];
#pragma unroll
            for (int mt = 0; mt < 4; mt++) {
                int row = wm * 64 + mt * 16 + (lane & 15);
                int ch = c0 + (lane >> 4);
                uint32_t addr = aBase + SW128((uint32_t)(row * 128 + ch * 16));
                LDSM_X4(af[mt][0], af[mt][1], af[mt][2], af[mt][3], addr);
            }
#pragma unroll
            for (int g = 0; g < 2; g++) {
                int row = wn * 32 + g * 16 + (lane & 7) + ((lane >> 4) << 3);
                int ch = c0 + ((lane >> 3) & 1);
                uint32_t addr = bBase + SW128((uint32_t)(row * 128 + ch * 16));
                LDSM_X4(bf[2 * g][0], bf[2 * g][1], bf[2 * g + 1][0], bf[2 * g + 1][1], addr);
            }
#pragma unroll
            for (int mt = 0; mt < 4; mt++)
#pragma unroll
                for (int nf = 0; nf < 4; nf++) mma_f16(acc[mt][nf], af[mt], bf[nf]);
        }
        // no bottom __syncthreads — top-of-iteration barrier provides the ordering
    }
#undef G_LOAD_STAGE

#pragma unroll
    for (int mt = 0; mt < 4; mt++) {
        int row0 = m0 + wm * 64 + mt * 16 + r;
#pragma unroll
        for (int nf = 0; nf < 4; nf++) {
            int col = n0 + wn * 32 + nf * 8 + 2 * cq;
            store_pair(C + (size_t)row0 * N + col, acc[mt][nf][0], acc[mt][nf][1]);
            store_pair(C + (size_t)(row0 + 8) * N + col, acc[mt][nf][2], acc[mt][nf][3]);
        }
    }
}

__global__ __launch_bounds__(GTHREADS, 2) void gemm_qkv_kernel(
    const __half* __restrict__ x,
    const __half* __restrict__ wq, const __half* __restrict__ wk, const __half* __restrict__ wv,
    __half* __restrict__ q, __half* __restrict__ k, __half* __restrict__ v) {
    extern __shared__ char smem[];
    const __half* B = (blockIdx.z == 0) ? wq : (blockIdx.z == 1) ? wk : wv;
    __half* C       = (blockIdx.z == 0) ? q  : (blockIdx.z == 1) ? k  : v;
    gemm_fp16_body<__half>(x, B, C, smem);
}

__global__ __launch_bounds__(GTHREADS, 2) void gemm_out_kernel(const __half* __restrict__ A,
                                                               const __half* __restrict__ B,
                                                               float* __restrict__ C) {
    extern __shared__ char smem[];
    gemm_fp16_body<float>(A, B, C, smem);
}

// ---------------------------------------------------------------------------
// RoPE (non-interleaved / chunk-half), in-place on fp16 Q and K.
// ---------------------------------------------------------------------------
__global__ void rope_kernel(__half* __restrict__ q, __half* __restrict__ k) {
    int t = blockIdx.x * blockDim.x + threadIdx.x;
    const int total = BATCH * SEQ * NHEAD * 64;
    if (t >= total) return;
    int j = t & 63;
    int h = (t >> 6) & (NHEAD - 1);
    int s = (t >> 10) & (SEQ - 1);
    int b = t >> 21;
    size_t off = ((size_t)(b * SEQ + s)) * DIM + h * HDIM + j;
    float inv = powf(10000.0f, -(float)(2 * j) * (1.0f / 128.0f));
    float ph = (float)s * inv;
    float sn, cs;
    sincosf(ph, &sn, &cs);
    float q1 = __half2float(q[off]), q2 = __half2float(q[off + 64]);
    q[off]      = __float2half_rn(q1 * cs - q2 * sn);
    q[off + 64] = __float2half_rn(q1 * sn + q2 * cs);
    float k1 = __half2float(k[off]), k2 = __half2float(k[off + 64]);
    k[off]      = __float2half_rn(k1 * cs - k2 * sn);
    k[off + 64] = __float2half_rn(k1 * sn + k2 * cs);
}

// ---------------------------------------------------------------------------
// Causal flash attention, fp16 mma. Grid: (S/64, H, B), 128 threads
// (4 warps x 16 q-rows). 32-key blocks. Q in registers; K via ldmatrix,
// V via ldmatrix.trans; P-fragments packed directly from S accumulators.
// ---------------------------------------------------------------------------
#define KPAD 136   // padded row stride in halfs (272 B) — conflict-free ldmatrix

__global__ __launch_bounds__(128) void flash_kernel(const __half* __restrict__ Q,
                                                    const __half* __restrict__ Kg,
                                                    const __half* __restrict__ Vg,
                                                    __half* __restrict__ O) {
    __shared__ __half Ks[32][KPAD];
    __shared__ __half Vs[32][KPAD];

    const int tid = threadIdx.x;
    const int warp = tid >> 5, lane = tid & 31;
    const int r = lane >> 2, cq = lane & 3;
    const int q0 = blockIdx.x * 64;
    const int h = blockIdx.y, b = blockIdx.z;
    const size_t head_off = (size_t)b * SEQ * DIM + (size_t)h * HDIM;
    const uint32_t uK = smem_u32(&Ks[0][0]);
    const uint32_t uV = smem_u32(&Vs[0][0]);

    // ---- Q fragments: 8 k16-chunks x 4 regs ----
    const __half* Qp = Q + head_off + (size_t)(q0 + warp * 16) * DIM;
    uint32_t aQ[8][4];
#pragma unroll
    for (int kc = 0; kc < 8; kc++) {
        aQ[kc][0] = *(const uint32_t*)(Qp + (size_t)r * DIM + kc * 16 + 2 * cq);
        aQ[kc][1] = *(const uint32_t*)(Qp + (size_t)(r + 8) * DIM + kc * 16 + 2 * cq);
        aQ[kc][2] = *(const uint32_t*)(Qp + (size_t)r * DIM + kc * 16 + 8 + 2 * cq);
        aQ[kc][3] = *(const uint32_t*)(Qp + (size_t)(r + 8) * DIM + kc * 16 + 8 + 2 * cq);
    }

    float o[16][4];
#pragma unroll
    for (int i = 0; i < 16; i++)
#pragma unroll
        for (int j = 0; j < 4; j++) o[i][j] = 0.f;
    float m0 = -1e30f, m1 = -1e30f, l0 = 0.f, l1 = 0.f;

    const int nkb = (q0 >> 5) + 2;
    for (int kb = 0; kb < nkb; kb++) {
        const int kstart = kb * 32;
        __syncthreads();

        // K,V tiles -> smem (uint4, coalesced; 512 chunks each, 4/thread)
        const __half* Kp = Kg + head_off + (size_t)kstart * DIM;
        const __half* Vp = Vg + head_off + (size_t)kstart * DIM;
#pragma unroll
        for (int i = 0; i < 4; i++) {
            int c = tid + i * 128;
            int row = c >> 4, ch = c & 15;
            *(uint4*)&Ks[row][ch * 8] = *(const uint4*)(Kp + (size_t)row * DIM + ch * 8);
            *(uint4*)&Vs[row][ch * 8] = *(const uint4*)(Vp + (size_t)row * DIM + ch * 8);
        }
        __syncthreads();

        // ---- S = Q K^T (16 rows x 32 keys per warp) ----
        float s[4][4];
#pragma unroll
        for (int nt = 0; nt < 4; nt++)
#pragma unroll
            for (int j = 0; j < 4; j++) s[nt][j] = 0.f;
#pragma unroll
        for (int kc = 0; kc < 8; kc++) {
            uint32_t bf[4][2];
#pragma unroll
            for (int g = 0; g < 2; g++) {
                int row = g * 16 + (lane & 7) + ((lane >> 4) << 3);
                int ch = kc * 2 + ((lane >> 3) & 1);
                uint32_t addr = uK + (uint32_t)(row * (KPAD * 2) + ch * 16);
                LDSM_X4(bf[2 * g][0], bf[2 * g][1], bf[2 * g + 1][0], bf[2 * g + 1][1], addr);
            }
#pragma unroll
            for (int nt = 0; nt < 4; nt++) mma_f16(s[nt], aQ[kc], bf[nt]);
        }

        const float scale = 0.08838834764831843f;  // 1/sqrt(128)
        const int qrow0 = q0 + warp * 16 + r;
        const bool need_mask = (kstart + 31 > q0 + warp * 16);
#pragma unroll
        for (int nt = 0; nt < 4; nt++) {
#pragma unroll
            for (int u = 0; u < 2; u++) {
                int key = kstart + nt * 8 + 2 * cq + u;
                s[nt][u] *= scale;
                s[nt][2 + u] *= scale;
                if (need_mask) {
                    if (key > qrow0) s[nt][u] = -1e30f;
                    if (key > qrow0 + 8) s[nt][2 + u] = -1e30f;
                }
            }
        }

        // ---- online softmax ----
        float mx0 = -1e30f, mx1 = -1e30f;
#pragma unroll
        for (int nt = 0; nt < 4; nt++) {
            mx0 = fmaxf(mx0, fmaxf(s[nt][0], s[nt][1]));
            mx1 = fmaxf(mx1, fmaxf(s[nt][2], s[nt][3]));
        }
        mx0 = fmaxf(mx0, __shfl_xor_sync(0xffffffffu, mx0, 1));
        mx0 = fmaxf(mx0, __shfl_xor_sync(0xffffffffu, mx0, 2));
        mx1 = fmaxf(mx1, __shfl_xor_sync(0xffffffffu, mx1, 1));
        mx1 = fmaxf(mx1, __shfl_xor_sync(0xffffffffu, mx1, 2));
        float mn0 = fmaxf(m0, mx0), mn1 = fmaxf(m1, mx1);
        float al0 = __expf(m0 - mn0), al1 = __expf(m1 - mn1);
        float sum0 = 0.f, sum1 = 0.f;
#pragma unroll
        for (int nt = 0; nt < 4; nt++) {
            s[nt][0] = __expf(s[nt][0] - mn0);
            s[nt][1] = __expf(s[nt][1] - mn0);
            s[nt][2] = __expf(s[nt][2] - mn1);
            s[nt][3] = __expf(s[nt][3] - mn1);
            sum0 += s[nt][0] + s[nt][1];
            sum1 += s[nt][2] + s[nt][3];
        }
        sum0 += __shfl_xor_sync(0xffffffffu, sum0, 1);
        sum0 += __shfl_xor_sync(0xffffffffu, sum0, 2);
        sum1 += __shfl_xor_sync(0xffffffffu, sum1, 1);
        sum1 += __shfl_xor_sync(0xffffffffu, sum1, 2);
        l0 = l0 * al0 + sum0;
        l1 = l1 * al1 + sum1;
        m0 = mn0;
        m1 = mn1;
#pragma unroll
        for (int nt = 0; nt < 16; nt++) {
            o[nt][0] *= al0;
            o[nt][1] *= al0;
            o[nt][2] *= al1;
            o[nt][3] *= al1;
        }

        // ---- O += P V : P fragments packed straight from S accumulators ----
#pragma unroll
        for (int g = 0; g < 2; g++) {
            uint32_t aP[4];
            aP[0] = packh2(s[2 * g][0], s[2 * g][1]);
            aP[1] = packh2(s[2 * g][2], s[2 * g][3]);
            aP[2] = packh2(s[2 * g + 1][0], s[2 * g + 1][1]);
            aP[3] = packh2(s[2 * g + 1][2], s[2 * g + 1][3]);
#pragma unroll
            for (int p = 0; p < 8; p++) {   // pairs of d-tiles
                uint32_t bv[2][2];
                int row = g * 16 + (lane & 7) + (((lane >> 3) & 1) << 3);
                int ch = 2 * p + (lane >> 4);
                uint32_t addr = uV + (uint32_t)(row * (KPAD * 2) + ch * 16);
                LDSM_X4_T(bv[0][0], bv[0][1], bv[1][0], bv[1][1], addr);
                mma_f16(o[2 * p], aP, bv[0]);
                mma_f16(o[2 * p + 1], aP, bv[1]);
            }
        }
    }

    const float inv0 = 1.f / l0, inv1 = 1.f / l1;
    __half* Op = O + head_off + (size_t)(q0 + warp * 16) * DIM;
#pragma unroll
    for (int nt = 0; nt < 16; nt++) {
        int col = nt * 8 + 2 * cq;
        store_pair(Op + (size_t)r * DIM + col, o[nt][0] * inv0, o[nt][1] * inv0);
        store_pair(Op + (size_t)(r + 8) * DIM + col, o[nt][2] * inv1, o[nt][3] * inv1);
    }
}

// ---------------------------------------------------------------------------
extern "C" void kernel_launch(void* const* d_in, const int* in_sizes, int n_in,
                              void* d_out, int out_size) {
    const float* x  = (const float*)d_in[0];
    const float* Wq = (const float*)d_in[1];
    const float* Wk = (const float*)d_in[2];
    const float* Wv = (const float*)d_in[3];
    const float* Wo = (const float*)d_in[4];
    float* out = (float*)d_out;

    __half *qp, *kp, *vp, *ap, *xr, *wqr, *wkr, *wvr, *wor;
    cudaGetSymbolAddress((void**)&qp, g_q);
    cudaGetSymbolAddress((void**)&kp, g_k);
    cudaGetSymbolAddress((void**)&vp, g_v);
    cudaGetSymbolAddress((void**)&ap, g_attn);
    cudaGetSymbolAddress((void**)&xr, g_xr);
    cudaGetSymbolAddress((void**)&wqr, g_wqr);
    cudaGetSymbolAddress((void**)&wkr, g_wkr);
    cudaGetSymbolAddress((void**)&wvr, g_wvr);
    cudaGetSymbolAddress((void**)&wor, g_wor);

    cudaFuncSetAttribute(gemm_qkv_kernel, cudaFuncAttributeMaxDynamicSharedMemorySize, GSMEM_BYTES);
    cudaFuncSetAttribute(gemm_out_kernel, cudaFuncAttributeMaxDynamicSharedMemorySize, GSMEM_BYTES);

    // One fused conversion launch: z=0 covers x (8192 blocks), z=1..4 weights (4096)
    convert_all_kernel<<<dim3(MROWS * DIM / 4 / 256, 1, 5), 256>>>(
        x, Wq, Wk, Wv, Wo, xr, wqr, wkr, wvr, wor);

    dim3 gqkv(DIM / GBN, MROWS / GBM, 3);  // (16, 32, 3)
    gemm_qkv_kernel<<<gqkv, GTHREADS, GSMEM_BYTES>>>(xr, wqr, wkr, wvr, qp, kp, vp);

    const int rope_threads = BATCH * SEQ * NHEAD * 64;
    rope_kernel<<<rope_threads / 256, 256>>>(qp, kp);

    flash_kernel<<<dim3(SEQ / 64, NHEAD, BATCH), 128>>>(qp, kp, vp, ap);

    gemm_out_kernel<<<dim3(DIM / GBN, MROWS / GBM), GTHREADS, GSMEM_BYTES>>>(ap, wor, out);
}

// round 10
// speedup vs baseline: 1.1612x; 1.0250x over previous
#include <cuda_runtime.h>
#include <cuda_fp16.h>
#include <cstdint>

#define DIM   2048
#define NHEAD 16
#define HDIM  128
#define BATCH 2
#define SEQ   2048
#define MROWS (BATCH*SEQ)   // 4096

// ---- fp16 GEMM tile config ----
#define GBM 128
#define GBN 128
#define GBK 64                         // 64 halfs = 128 bytes = one swizzle row
#define GSTAGES 3
#define STAGE_T_BYTES (128 * 128)      // one operand tile per stage: 16384 B
#define GSMEM_BYTES (GSTAGES * 2 * STAGE_T_BYTES)   // 98304
#define GTHREADS 256

#define SW128(o) ((o) ^ ((((uint32_t)(o)) >> 3) & 0x70u))

// Scratch (allocation-free rule: __device__ globals)
__device__ __half g_q[(size_t)MROWS * DIM];
__device__ __half g_k[(size_t)MROWS * DIM];
__device__ __half g_v[(size_t)MROWS * DIM];
__device__ __half g_attn[(size_t)MROWS * DIM];
__device__ __half g_xr[(size_t)MROWS * DIM];
__device__ __half g_wqr[(size_t)DIM * DIM];
__device__ __half g_wkr[(size_t)DIM * DIM];
__device__ __half g_wvr[(size_t)DIM * DIM];
__device__ __half g_wor[(size_t)DIM * DIM];

// ---------------------------------------------------------------------------
// PTX helpers
// ---------------------------------------------------------------------------
__device__ __forceinline__ void mma_f16(float c[4], const uint32_t a[4], const uint32_t b[2]) {
    asm volatile(
        "mma.sync.aligned.m16n8k16.row.col.f32.f16.f16.f32 "
        "{%0,%1,%2,%3}, {%4,%5,%6,%7}, {%8,%9}, {%0,%1,%2,%3};\n"
        : "+f"(c[0]), "+f"(c[1]), "+f"(c[2]), "+f"(c[3])
        : "r"(a[0]), "r"(a[1]), "r"(a[2]), "r"(a[3]), "r"(b[0]), "r"(b[1]));
}

#define LDSM_X4(r0, r1, r2, r3, addr)                                       \
    asm volatile("ldmatrix.sync.aligned.m8n8.x4.shared.b16 {%0,%1,%2,%3}, [%4];" \
                 : "=r"(r0), "=r"(r1), "=r"(r2), "=r"(r3) : "r"(addr))

#define LDSM_X4_T(r0, r1, r2, r3, addr)                                     \
    asm volatile("ldmatrix.sync.aligned.m8n8.x4.trans.shared.b16 {%0,%1,%2,%3}, [%4];" \
                 : "=r"(r0), "=r"(r1), "=r"(r2), "=r"(r3) : "r"(addr))

__device__ __forceinline__ void cp16(void* dst, const void* src) {
    uint32_t s = (uint32_t)__cvta_generic_to_shared(dst);
    asm volatile("cp.async.cg.shared.global [%0], [%1], 16;" :: "r"(s), "l"(src));
}

__device__ __forceinline__ uint32_t smem_u32(const void* p) {
    return (uint32_t)__cvta_generic_to_shared(p);
}

__device__ __forceinline__ uint32_t packh2(float a, float b) {
    __half2 h = __floats2half2_rn(a, b);
    return *(uint32_t*)&h;
}

__device__ __forceinline__ void store_pair(__half* p, float a, float b) {
    *(uint32_t*)p = packh2(a, b);
}
__device__ __forceinline__ void store_pair(float* p, float a, float b) {
    *(float2*)p = make_float2(a, b);
}

// ---------------------------------------------------------------------------
// Fused f32 -> f16 conversion: grid.z selects tensor (0=x, 1..4=weights)
// ---------------------------------------------------------------------------
__global__ void convert_all_kernel(const float* __restrict__ x,
                                   const float* __restrict__ wq, const float* __restrict__ wk,
                                   const float* __restrict__ wv, const float* __restrict__ wo,
                                   __half* __restrict__ xr,
                                   __half* __restrict__ wqr, __half* __restrict__ wkr,
                                   __half* __restrict__ wvr, __half* __restrict__ wor) {
    const int z = blockIdx.z;
    const int nw4 = DIM * DIM / 4;
    if (z > 0 && blockIdx.x >= (unsigned)(nw4 / 256)) return;
    int t = blockIdx.x * 256 + threadIdx.x;
    const float* in;
    __half* out;
    switch (z) {
        case 0: in = x;  out = xr;  break;
        case 1: in = wq; out = wqr; break;
        case 2: in = wk; out = wkr; break;
        case 3: in = wv; out = wvr; break;
        default: in = wo; out = wor; break;
    }
    float4 v = ((const float4*)in)[t];
    ((uint2*)out)[t] = make_uint2(packh2(v.x, v.y), packh2(v.z, v.w));
}

// ---------------------------------------------------------------------------
// fp16 TN GEMM: C[m,n] = sum_k A[m,k]*B[n,k], f32 accumulate.
// CTA 128x128, BK=64 halfs, 8 warps (warp tile 64x32), 3-stage cp.async,
// SW128-swizzled smem, ldmatrix fragment loads. ONE barrier per k-step.
// ---------------------------------------------------------------------------
template <typename OutT>
__device__ __forceinline__ void gemm_fp16_body(const __half* __restrict__ A,
                                               const __half* __restrict__ B,
                                               OutT* __restrict__ C,
                                               char* smem) {
    const int K = DIM, N = DIM;
    const int tid = threadIdx.x;
    const int warp = tid >> 5, lane = tid & 31;
    const int m0 = blockIdx.y * GBM, n0 = blockIdx.x * GBN;
    const int wm = warp >> 2, wn = warp & 3;      // 2x4 warps -> warp tile 64x32
    const int r = lane >> 2, cq = lane & 3;

    char* As = smem;
    char* Bs = smem + GSTAGES * STAGE_T_BYTES;
    const uint32_t uA = smem_u32(As);
    const uint32_t uB = smem_u32(Bs);

    float acc[4][4][4];
#pragma unroll
    for (int mt = 0; mt < 4; mt++)
#pragma unroll
        for (int nf = 0; nf < 4; nf++)
#pragma unroll
            for (int q = 0; q < 4; q++) acc[mt][nf][q] = 0.f;

#define G_LOAD_STAGE(slot, kt)                                                     \
    do {                                                                           \
        const __half* Ag = A + (size_t)m0 * K + (size_t)(kt) * GBK;                \
        const __half* Bg = B + (size_t)n0 * K + (size_t)(kt) * GBK;                \
        _Pragma("unroll")                                                          \
        for (int i = 0; i < 4; i++) {                                              \
            int c = tid + i * GTHREADS;                                            \
            int row = c >> 3, ch = c & 7;                                          \
            uint32_t sw = SW128((uint32_t)(row * 128 + ch * 16));                  \
            cp16(As + (slot) * STAGE_T_BYTES + sw, Ag + (size_t)row * K + ch * 8); \
            cp16(Bs + (slot) * STAGE_T_BYTES + sw, Bg + (size_t)row * K + ch * 8); \
        }                                                                          \
    } while (0)

    G_LOAD_STAGE(0, 0);
    asm volatile("cp.async.commit_group;");
    G_LOAD_STAGE(1, 1);
    asm volatile("cp.async.commit_group;");

    const int KT = K / GBK;  // 32
    for (int kt = 0; kt < KT; kt++) {
        asm volatile("cp.async.wait_group 1;");
        __syncthreads();
        int pf = kt + GSTAGES - 1;
        if (pf < KT) G_LOAD_STAGE(pf % GSTAGES, pf);
        asm volatile("cp.async.commit_group;");

        const uint32_t aBase = uA + (kt % GSTAGES) * STAGE_T_BYTES;
        const uint32_t bBase = uB + (kt % GSTAGES) * STAGE_T_BYTES;

#pragma unroll
        for (int kk = 0; kk < 4; kk++) {          // 4 x k16 per stage
            const int c0 = kk * 2;
            uint32_t af[4][4], bf[4][2];
#pragma unroll
            for (int mt = 0; mt < 4; mt++) {
                int row = wm * 64 + mt * 16 + (lane & 15);
                int ch = c0 + (lane >> 4);
                uint32_t addr = aBase + SW128((uint32_t)(row * 128 + ch * 16));
                LDSM_X4(af[mt][0], af[mt][1], af[mt][2], af[mt][3], addr);
            }
#pragma unroll
            for (int g = 0; g < 2; g++) {
                int row = wn * 32 + g * 16 + (lane & 7) + ((lane >> 4) << 3);
                int ch = c0 + ((lane >> 3) & 1);
                uint32_t addr = bBase + SW128((uint32_t)(row * 128 + ch * 16));
                LDSM_X4(bf[2 * g][0], bf[2 * g][1], bf[2 * g + 1][0], bf[2 * g + 1][1], addr);
            }
#pragma unroll
            for (int mt = 0; mt < 4; mt++)
#pragma unroll
                for (int nf = 0; nf < 4; nf++) mma_f16(acc[mt][nf], af[mt], bf[nf]);
        }
        // no bottom __syncthreads — top-of-iteration barrier provides the ordering
    }
#undef G_LOAD_STAGE

#pragma unroll
    for (int mt = 0; mt < 4; mt++) {
        int row0 = m0 + wm * 64 + mt * 16 + r;
#pragma unroll
        for (int nf = 0; nf < 4; nf++) {
            int col = n0 + wn * 32 + nf * 8 + 2 * cq;
            store_pair(C + (size_t)row0 * N + col, acc[mt][nf][0], acc[mt][nf][1]);
            store_pair(C + (size_t)(row0 + 8) * N + col, acc[mt][nf][2], acc[mt][nf][3]);
        }
    }
}

__global__ __launch_bounds__(GTHREADS, 2) void gemm_qkv_kernel(
    const __half* __restrict__ x,
    const __half* __restrict__ wq, const __half* __restrict__ wk, const __half* __restrict__ wv,
    __half* __restrict__ q, __half* __restrict__ k, __half* __restrict__ v) {
    extern __shared__ char smem[];
    const __half* B = (blockIdx.z == 0) ? wq : (blockIdx.z == 1) ? wk : wv;
    __half* C       = (blockIdx.z == 0) ? q  : (blockIdx.z == 1) ? k  : v;
    gemm_fp16_body<__half>(x, B, C, smem);
}

__global__ __launch_bounds__(GTHREADS, 2) void gemm_out_kernel(const __half* __restrict__ A,
                                                               const __half* __restrict__ B,
                                                               float* __restrict__ C) {
    extern __shared__ char smem[];
    gemm_fp16_body<float>(A, B, C, smem);
}

// ---------------------------------------------------------------------------
// RoPE (non-interleaved / chunk-half), in-place on fp16 Q and K.
// ---------------------------------------------------------------------------
__global__ void rope_kernel(__half* __restrict__ q, __half* __restrict__ k) {
    int t = blockIdx.x * blockDim.x + threadIdx.x;
    const int total = BATCH * SEQ * NHEAD * 64;
    if (t >= total) return;
    int j = t & 63;
    int h = (t >> 6) & (NHEAD - 1);
    int s = (t >> 10) & (SEQ - 1);
    int b = t >> 21;
    size_t off = ((size_t)(b * SEQ + s)) * DIM + h * HDIM + j;
    float inv = powf(10000.0f, -(float)(2 * j) * (1.0f / 128.0f));
    float ph = (float)s * inv;
    float sn, cs;
    sincosf(ph, &sn, &cs);
    float q1 = __half2float(q[off]), q2 = __half2float(q[off + 64]);
    q[off]      = __float2half_rn(q1 * cs - q2 * sn);
    q[off + 64] = __float2half_rn(q1 * sn + q2 * cs);
    float k1 = __half2float(k[off]), k2 = __half2float(k[off + 64]);
    k[off]      = __float2half_rn(k1 * cs - k2 * sn);
    k[off + 64] = __float2half_rn(k1 * sn + k2 * cs);
}

// ---------------------------------------------------------------------------
// Causal flash attention, fp16 mma. Grid: (S/64, H, B), 128 threads
// (4 warps x 16 q-rows). 32-key blocks, 2-stage cp.async double-buffered KV:
// prefetch block kb+1 while computing kb. Q in registers; K via ldmatrix,
// V via ldmatrix.trans; P-fragments packed directly from S accumulators.
// ---------------------------------------------------------------------------
#define KPAD 136   // padded row stride in halfs (272 B) — conflict-free ldmatrix
#define KV_STAGE_HALFS (32 * KPAD)

__global__ __launch_bounds__(128) void flash_kernel(const __half* __restrict__ Q,
                                                    const __half* __restrict__ Kg,
                                                    const __half* __restrict__ Vg,
                                                    __half* __restrict__ O) {
    __shared__ __half Ks[2][32][KPAD];
    __shared__ __half Vs[2][32][KPAD];

    const int tid = threadIdx.x;
    const int warp = tid >> 5, lane = tid & 31;
    const int r = lane >> 2, cq = lane & 3;
    const int q0 = blockIdx.x * 64;
    const int h = blockIdx.y, b = blockIdx.z;
    const size_t head_off = (size_t)b * SEQ * DIM + (size_t)h * HDIM;
    const uint32_t uK = smem_u32(&Ks[0][0][0]);
    const uint32_t uV = smem_u32(&Vs[0][0][0]);

    // Per-thread cp.async slice: 4 chunks per tensor (512 chunks / 128 threads)
    const int ld_row = tid >> 4;           // 0..7  (+8*i)
    const int ld_ch  = tid & 15;           // 16B chunk within row

#define KV_LOAD_STAGE(st, kstart_)                                                \
    do {                                                                          \
        const __half* Kp = Kg + head_off + (size_t)(kstart_) * DIM;               \
        const __half* Vp = Vg + head_off + (size_t)(kstart_) * DIM;               \
        _Pragma("unroll")                                                         \
        for (int i = 0; i < 4; i++) {                                             \
            int row = ld_row + i * 8;                                             \
            cp16(&Ks[st][row][ld_ch * 8], Kp + (size_t)row * DIM + ld_ch * 8);    \
            cp16(&Vs[st][row][ld_ch * 8], Vp + (size_t)row * DIM + ld_ch * 8);    \
        }                                                                         \
    } while (0)

    // ---- Q fragments: 8 k16-chunks x 4 regs ----
    const __half* Qp = Q + head_off + (size_t)(q0 + warp * 16) * DIM;
    uint32_t aQ[8][4];
#pragma unroll
    for (int kc = 0; kc < 8; kc++) {
        aQ[kc][0] = *(const uint32_t*)(Qp + (size_t)r * DIM + kc * 16 + 2 * cq);
        aQ[kc][1] = *(const uint32_t*)(Qp + (size_t)(r + 8) * DIM + kc * 16 + 2 * cq);
        aQ[kc][2] = *(const uint32_t*)(Qp + (size_t)r * DIM + kc * 16 + 8 + 2 * cq);
        aQ[kc][3] = *(const uint32_t*)(Qp + (size_t)(r + 8) * DIM + kc * 16 + 8 + 2 * cq);
    }

    float o[16][4];
#pragma unroll
    for (int i = 0; i < 16; i++)
#pragma unroll
        for (int j = 0; j < 4; j++) o[i][j] = 0.f;
    float m0 = -1e30f, m1 = -1e30f, l0 = 0.f, l1 = 0.f;

    const int nkb = (q0 >> 5) + 2;

    KV_LOAD_STAGE(0, 0);
    asm volatile("cp.async.commit_group;");

    for (int kb = 0; kb < nkb; kb++) {
        const int kstart = kb * 32;
        const int st = kb & 1;

        // All warps done with buffer (kb-1)&1 == (kb+1)&1 before refilling it.
        __syncthreads();
        if (kb + 1 < nkb) KV_LOAD_STAGE((kb + 1) & 1, kstart + 32);
        asm volatile("cp.async.commit_group;");
        asm volatile("cp.async.wait_group 1;");   // stage kb resident
        __syncthreads();

        const uint32_t kBase = uK + st * (KV_STAGE_HALFS * 2);
        const uint32_t vBase = uV + st * (KV_STAGE_HALFS * 2);

        // ---- S = Q K^T (16 rows x 32 keys per warp) ----
        float s[4][4];
#pragma unroll
        for (int nt = 0; nt < 4; nt++)
#pragma unroll
            for (int j = 0; j < 4; j++) s[nt][j] = 0.f;
#pragma unroll
        for (int kc = 0; kc < 8; kc++) {
            uint32_t bf[4][2];
#pragma unroll
            for (int g = 0; g < 2; g++) {
                int row = g * 16 + (lane & 7) + ((lane >> 4) << 3);
                int ch = kc * 2 + ((lane >> 3) & 1);
                uint32_t addr = kBase + (uint32_t)(row * (KPAD * 2) + ch * 16);
                LDSM_X4(bf[2 * g][0], bf[2 * g][1], bf[2 * g + 1][0], bf[2 * g + 1][1], addr);
            }
#pragma unroll
            for (int nt = 0; nt < 4; nt++) mma_f16(s[nt], aQ[kc], bf[nt]);
        }

        const float scale = 0.08838834764831843f;  // 1/sqrt(128)
        const int qrow0 = q0 + warp * 16 + r;
        const bool need_mask = (kstart + 31 > q0 + warp * 16);
#pragma unroll
        for (int nt = 0; nt < 4; nt++) {
#pragma unroll
            for (int u = 0; u < 2; u++) {
                int key = kstart + nt * 8 + 2 * cq + u;
                s[nt][u] *= scale;
                s[nt][2 + u] *= scale;
                if (need_mask) {
                    if (key > qrow0) s[nt][u] = -1e30f;
                    if (key > qrow0 + 8) s[nt][2 + u] = -1e30f;
                }
            }
        }

        // ---- online softmax ----
        float mx0 = -1e30f, mx1 = -1e30f;
#pragma unroll
        for (int nt = 0; nt < 4; nt++) {
            mx0 = fmaxf(mx0, fmaxf(s[nt][0], s[nt][1]));
            mx1 = fmaxf(mx1, fmaxf(s[nt][2], s[nt][3]));
        }
        mx0 = fmaxf(mx0, __shfl_xor_sync(0xffffffffu, mx0, 1));
        mx0 = fmaxf(mx0, __shfl_xor_sync(0xffffffffu, mx0, 2));
        mx1 = fmaxf(mx1, __shfl_xor_sync(0xffffffffu, mx1, 1));
        mx1 = fmaxf(mx1, __shfl_xor_sync(0xffffffffu, mx1, 2));
        float mn0 = fmaxf(m0, mx0), mn1 = fmaxf(m1, mx1);
        float al0 = __expf(m0 - mn0), al1 = __expf(m1 - mn1);
        float sum0 = 0.f, sum1 = 0.f;
#pragma unroll
        for (int nt = 0; nt < 4; nt++) {
            s[nt][0] = __expf(s[nt][0] - mn0);
            s[nt][1] = __expf(s[nt][1] - mn0);
            s[nt][2] = __expf(s[nt][2] - mn1);
            s[nt][3] = __expf(s[nt][3] - mn1);
            sum0 += s[nt][0] + s[nt][1];
            sum1 += s[nt][2] + s[nt][3];
        }
        sum0 += __shfl_xor_sync(0xffffffffu, sum0, 1);
        sum0 += __shfl_xor_sync(0xffffffffu, sum0, 2);
        sum1 += __shfl_xor_sync(0xffffffffu, sum1, 1);
        sum1 += __shfl_xor_sync(0xffffffffu, sum1, 2);
        l0 = l0 * al0 + sum0;
        l1 = l1 * al1 + sum1;
        m0 = mn0;
        m1 = mn1;
#pragma unroll
        for (int nt = 0; nt < 16; nt++) {
            o[nt][0] *= al0;
            o[nt][1] *= al0;
            o[nt][2] *= al1;
            o[nt][3] *= al1;
        }

        // ---- O += P V : P fragments packed straight from S accumulators ----
#pragma unroll
        for (int g = 0; g < 2; g++) {
            uint32_t aP[4];
            aP[0] = packh2(s[2 * g][0], s[2 * g][1]);
            aP[1] = packh2(s[2 * g][2], s[2 * g][3]);
            aP[2] = packh2(s[2 * g + 1][0], s[2 * g + 1][1]);
            aP[3] = packh2(s[2 * g + 1][2], s[2 * g + 1][3]);
#pragma unroll
            for (int p = 0; p < 8; p++) {   // pairs of d-tiles
                uint32_t bv[2][2];
                int row = g * 16 + (lane & 7) + (((lane >> 3) & 1) << 3);
                int ch = 2 * p + (lane >> 4);
                uint32_t addr = vBase + (uint32_t)(row * (KPAD * 2) + ch * 16);
                LDSM_X4_T(bv[0][0], bv[0][1], bv[1][0], bv[1][1], addr);
                mma_f16(o[2 * p], aP, bv[0]);
                mma_f16(o[2 * p + 1], aP, bv[1]);
            }
        }
    }
#undef KV_LOAD_STAGE

    const float inv0 = 1.f / l0, inv1 = 1.f / l1;
    __half* Op = O + head_off + (size_t)(q0 + warp * 16) * DIM;
#pragma unroll
    for (int nt = 0; nt < 16; nt++) {
        int col = nt * 8 + 2 * cq;
        store_pair(Op + (size_t)r * DIM + col, o[nt][0] * inv0, o[nt][1] * inv0);
        store_pair(Op + (size_t)(r + 8) * DIM + col, o[nt][2] * inv1, o[nt][3] * inv1);
    }
}

// ---------------------------------------------------------------------------
extern "C" void kernel_launch(void* const* d_in, const int* in_sizes, int n_in,
                              void* d_out, int out_size) {
    const float* x  = (const float*)d_in[0];
    const float* Wq = (const float*)d_in[1];
    const float* Wk = (const float*)d_in[2];
    const float* Wv = (const float*)d_in[3];
    const float* Wo = (const float*)d_in[4];
    float* out = (float*)d_out;

    __half *qp, *kp, *vp, *ap, *xr, *wqr, *wkr, *wvr, *wor;
    cudaGetSymbolAddress((void**)&qp, g_q);
    cudaGetSymbolAddress((void**)&kp, g_k);
    cudaGetSymbolAddress((void**)&vp, g_v);
    cudaGetSymbolAddress((void**)&ap, g_attn);
    cudaGetSymbolAddress((void**)&xr, g_xr);
    cudaGetSymbolAddress((void**)&wqr, g_wqr);
    cudaGetSymbolAddress((void**)&wkr, g_wkr);
    cudaGetSymbolAddress((void**)&wvr, g_wvr);
    cudaGetSymbolAddress((void**)&wor, g_wor);

    cudaFuncSetAttribute(gemm_qkv_kernel, cudaFuncAttributeMaxDynamicSharedMemorySize, GSMEM_BYTES);
    cudaFuncSetAttribute(gemm_out_kernel, cudaFuncAttributeMaxDynamicSharedMemorySize, GSMEM_BYTES);

    // One fused conversion launch: z=0 covers x (8192 blocks), z=1..4 weights (4096)
    convert_all_kernel<<<dim3(MROWS * DIM / 4 / 256, 1, 5), 256>>>(
        x, Wq, Wk, Wv, Wo, xr, wqr, wkr, wvr, wor);

    dim3 gqkv(DIM / GBN, MROWS / GBM, 3);  // (16, 32, 3)
    gemm_qkv_kernel<<<gqkv, GTHREADS, GSMEM_BYTES>>>(xr, wqr, wkr, wvr, qp, kp, vp);

    const int rope_threads = BATCH * SEQ * NHEAD * 64;
    rope_kernel<<<rope_threads / 256, 256>>>(qp, kp);

    flash_kernel<<<dim3(SEQ / 64, NHEAD, BATCH), 128>>>(qp, kp, vp, ap);

    gemm_out_kernel<<<dim3(DIM / GBN, MROWS / GBM), GTHREADS, GSMEM_BYTES>>>(ap, wor, out);
}

// round 11
// speedup vs baseline: 1.1678x; 1.0057x over previous
#include <cuda_runtime.h>
#include <cuda_fp16.h>
#include <cstdint>

#define DIM   2048
#define NHEAD 16
#define HDIM  128
#define BATCH 2
#define SEQ   2048
#define MROWS (BATCH*SEQ)   // 4096

// ---- fp16 GEMM tile config ----
#define GBM 128
#define GBN 128
#define GBK 64                         // 64 halfs = 128 bytes = one swizzle row
#define GSTAGES 3
#define STAGE_T_BYTES (128 * 128)      // one operand tile per stage: 16384 B
#define GSMEM_BYTES (GSTAGES * 2 * STAGE_T_BYTES)   // 98304
#define GTHREADS 256

#define SW128(o) ((o) ^ ((((uint32_t)(o)) >> 3) & 0x70u))

// Scratch (allocation-free rule: __device__ globals)
__device__ __half g_q[(size_t)MROWS * DIM];
__device__ __half g_k[(size_t)MROWS * DIM];
__device__ __half g_v[(size_t)MROWS * DIM];
__device__ __half g_attn[(size_t)MROWS * DIM];
__device__ __half g_xr[(size_t)MROWS * DIM];
__device__ __half g_wqr[(size_t)DIM * DIM];
__device__ __half g_wkr[(size_t)DIM * DIM];
__device__ __half g_wvr[(size_t)DIM * DIM];
__device__ __half g_wor[(size_t)DIM * DIM];

// ---------------------------------------------------------------------------
// PTX helpers
// ---------------------------------------------------------------------------
__device__ __forceinline__ void mma_f16(float c[4], const uint32_t a[4], const uint32_t b[2]) {
    asm volatile(
        "mma.sync.aligned.m16n8k16.row.col.f32.f16.f16.f32 "
        "{%0,%1,%2,%3}, {%4,%5,%6,%7}, {%8,%9}, {%0,%1,%2,%3};\n"
        : "+f"(c[0]), "+f"(c[1]), "+f"(c[2]), "+f"(c[3])
        : "r"(a[0]), "r"(a[1]), "r"(a[2]), "r"(a[3]), "r"(b[0]), "r"(b[1]));
}

#define LDSM_X4(r0, r1, r2, r3, addr)                                       \
    asm volatile("ldmatrix.sync.aligned.m8n8.x4.shared.b16 {%0,%1,%2,%3}, [%4];" \
                 : "=r"(r0), "=r"(r1), "=r"(r2), "=r"(r3) : "r"(addr))

#define LDSM_X4_T(r0, r1, r2, r3, addr)                                     \
    asm volatile("ldmatrix.sync.aligned.m8n8.x4.trans.shared.b16 {%0,%1,%2,%3}, [%4];" \
                 : "=r"(r0), "=r"(r1), "=r"(r2), "=r"(r3) : "r"(addr))

__device__ __forceinline__ void cp16(void* dst, const void* src) {
    uint32_t s = (uint32_t)__cvta_generic_to_shared(dst);
    asm volatile("cp.async.cg.shared.global [%0], [%1], 16;" :: "r"(s), "l"(src));
}

__device__ __forceinline__ uint32_t smem_u32(const void* p) {
    return (uint32_t)__cvta_generic_to_shared(p);
}

__device__ __forceinline__ uint32_t packh2(float a, float b) {
    __half2 h = __floats2half2_rn(a, b);
    return *(uint32_t*)&h;
}

__device__ __forceinline__ void store_pair(__half* p, float a, float b) {
    *(uint32_t*)p = packh2(a, b);
}
__device__ __forceinline__ void store_pair(float* p, float a, float b) {
    *(float2*)p = make_float2(a, b);
}

// ---------------------------------------------------------------------------
// Fused f32 -> f16 conversion: grid.z selects tensor (0=x, 1..4=weights)
// ---------------------------------------------------------------------------
__global__ void convert_all_kernel(const float* __restrict__ x,
                                   const float* __restrict__ wq, const float* __restrict__ wk,
                                   const float* __restrict__ wv, const float* __restrict__ wo,
                                   __half* __restrict__ xr,
                                   __half* __restrict__ wqr, __half* __restrict__ wkr,
                                   __half* __restrict__ wvr, __half* __restrict__ wor) {
    const int z = blockIdx.z;
    const int nw4 = DIM * DIM / 4;
    if (z > 0 && blockIdx.x >= (unsigned)(nw4 / 256)) return;
    int t = blockIdx.x * 256 + threadIdx.x;
    const float* in;
    __half* out;
    switch (z) {
        case 0: in = x;  out = xr;  break;
        case 1: in = wq; out = wqr; break;
        case 2: in = wk; out = wkr; break;
        case 3: in = wv; out = wvr; break;
        default: in = wo; out = wor; break;
    }
    float4 v = ((const float4*)in)[t];
    ((uint2*)out)[t] = make_uint2(packh2(v.x, v.y), packh2(v.z, v.w));
}

// ---------------------------------------------------------------------------
// fp16 TN GEMM: C[m,n] = sum_k A[m,k]*B[n,k], f32 accumulate.
// CTA 128x128, BK=64 halfs, 8 warps (warp tile 64x32), 3-stage cp.async,
// SW128-swizzled smem, ldmatrix fragment loads. ONE barrier per k-step.
// ---------------------------------------------------------------------------
template <typename OutT>
__device__ __forceinline__ void gemm_fp16_body(const __half* __restrict__ A,
                                               const __half* __restrict__ B,
                                               OutT* __restrict__ C,
                                               char* smem) {
    const int K = DIM, N = DIM;
    const int tid = threadIdx.x;
    const int warp = tid >> 5, lane = tid & 31;
    const int m0 = blockIdx.y * GBM, n0 = blockIdx.x * GBN;
    const int wm = warp >> 2, wn = warp & 3;      // 2x4 warps -> warp tile 64x32
    const int r = lane >> 2, cq = lane & 3;

    char* As = smem;
    char* Bs = smem + GSTAGES * STAGE_T_BYTES;
    const uint32_t uA = smem_u32(As);
    const uint32_t uB = smem_u32(Bs);

    float acc[4][4][4];
#pragma unroll
    for (int mt = 0; mt < 4; mt++)
#pragma unroll
        for (int nf = 0; nf < 4; nf++)
#pragma unroll
            for (int q = 0; q < 4; q++) acc[mt][nf][q] = 0.f;

#define G_LOAD_STAGE(slot, kt)                                                     \
    do {                                                                           \
        const __half* Ag = A + (size_t)m0 * K + (size_t)(kt) * GBK;                \
        const __half* Bg = B + (size_t)n0 * K + (size_t)(kt) * GBK;                \
        _Pragma("unroll")                                                          \
        for (int i = 0; i < 4; i++) {                                              \
            int c = tid + i * GTHREADS;                                            \
            int row = c >> 3, ch = c & 7;                                          \
            uint32_t sw = SW128((uint32_t)(row * 128 + ch * 16));                  \
            cp16(As + (slot) * STAGE_T_BYTES + sw, Ag + (size_t)row * K + ch * 8); \
            cp16(Bs + (slot) * STAGE_T_BYTES + sw, Bg + (size_t)row * K + ch * 8); \
        }                                                                          \
    } while (0)

    G_LOAD_STAGE(0, 0);
    asm volatile("cp.async.commit_group;");
    G_LOAD_STAGE(1, 1);
    asm volatile("cp.async.commit_group;");

    const int KT = K / GBK;  // 32
    for (int kt = 0; kt < KT; kt++) {
        asm volatile("cp.async.wait_group 1;");
        __syncthreads();
        int pf = kt + GSTAGES - 1;
        if (pf < KT) G_LOAD_STAGE(pf % GSTAGES, pf);
        asm volatile("cp.async.commit_group;");

        const uint32_t aBase = uA + (kt % GSTAGES) * STAGE_T_BYTES;
        const uint32_t bBase = uB + (kt % GSTAGES) * STAGE_T_BYTES;

#pragma unroll
        for (int kk = 0; kk < 4; kk++) {          // 4 x k16 per stage
            const int c0 = kk * 2;
            uint32_t af[4][4], bf[4][2];
#pragma unroll
            for (int mt = 0; mt < 4; mt++) {
                int row = wm * 64 + mt * 16 + (lane & 15);
                int ch = c0 + (lane >> 4);
                uint32_t addr = aBase + SW128((uint32_t)(row * 128 + ch * 16));
                LDSM_X4(af[mt][0], af[mt][1], af[mt][2], af[mt][3], addr);
            }
#pragma unroll
            for (int g = 0; g < 2; g++) {
                int row = wn * 32 + g * 16 + (lane & 7) + ((lane >> 4) << 3);
                int ch = c0 + ((lane >> 3) & 1);
                uint32_t addr = bBase + SW128((uint32_t)(row * 128 + ch * 16));
                LDSM_X4(bf[2 * g][0], bf[2 * g][1], bf[2 * g + 1][0], bf[2 * g + 1][1], addr);
            }
#pragma unroll
            for (int mt = 0; mt < 4; mt++)
#pragma unroll
                for (int nf = 0; nf < 4; nf++) mma_f16(acc[mt][nf], af[mt], bf[nf]);
        }
        // no bottom __syncthreads — top-of-iteration barrier provides the ordering
    }
#undef G_LOAD_STAGE

#pragma unroll
    for (int mt = 0; mt < 4; mt++) {
        int row0 = m0 + wm * 64 + mt * 16 + r;
#pragma unroll
        for (int nf = 0; nf < 4; nf++) {
            int col = n0 + wn * 32 + nf * 8 + 2 * cq;
            store_pair(C + (size_t)row0 * N + col, acc[mt][nf][0], acc[mt][nf][1]);
            store_pair(C + (size_t)(row0 + 8) * N + col, acc[mt][nf][2], acc[mt][nf][3]);
        }
    }
}

__global__ __launch_bounds__(GTHREADS, 2) void gemm_qkv_kernel(
    const __half* __restrict__ x,
    const __half* __restrict__ wq, const __half* __restrict__ wk, const __half* __restrict__ wv,
    __half* __restrict__ q, __half* __restrict__ k, __half* __restrict__ v) {
    extern __shared__ char smem[];
    const __half* B = (blockIdx.z == 0) ? wq : (blockIdx.z == 1) ? wk : wv;
    __half* C       = (blockIdx.z == 0) ? q  : (blockIdx.z == 1) ? k  : v;
    gemm_fp16_body<__half>(x, B, C, smem);
}

__global__ __launch_bounds__(GTHREADS, 2) void gemm_out_kernel(const __half* __restrict__ A,
                                                               const __half* __restrict__ B,
                                                               float* __restrict__ C) {
    extern __shared__ char smem[];
    gemm_fp16_body<float>(A, B, C, smem);
}

// ---------------------------------------------------------------------------
// RoPE (non-interleaved / chunk-half), in-place on fp16 Q and K.
// ---------------------------------------------------------------------------
__global__ void rope_kernel(__half* __restrict__ q, __half* __restrict__ k) {
    int t = blockIdx.x * blockDim.x + threadIdx.x;
    const int total = BATCH * SEQ * NHEAD * 64;
    if (t >= total) return;
    int j = t & 63;
    int h = (t >> 6) & (NHEAD - 1);
    int s = (t >> 10) & (SEQ - 1);
    int b = t >> 21;
    size_t off = ((size_t)(b * SEQ + s)) * DIM + h * HDIM + j;
    float inv = powf(10000.0f, -(float)(2 * j) * (1.0f / 128.0f));
    float ph = (float)s * inv;
    float sn, cs;
    sincosf(ph, &sn, &cs);
    float q1 = __half2float(q[off]), q2 = __half2float(q[off + 64]);
    q[off]      = __float2half_rn(q1 * cs - q2 * sn);
    q[off + 64] = __float2half_rn(q1 * sn + q2 * cs);
    float k1 = __half2float(k[off]), k2 = __half2float(k[off + 64]);
    k[off]      = __float2half_rn(k1 * cs - k2 * sn);
    k[off + 64] = __float2half_rn(k1 * sn + k2 * cs);
}

// ---------------------------------------------------------------------------
// Causal flash attention, fp16 mma. Grid: (S/64, H, B), 128 threads
// (4 warps x 16 q-rows). 64-key KV blocks, 2-stage cp.async double buffer
// (dynamic smem, 68 KB). Per-block fixed costs (o-rescale, shfl reductions,
// barriers) amortized over 2x keys vs the 32-key version.
// ---------------------------------------------------------------------------
#define KPAD 136                              // padded row stride in halfs
#define FKEYS 64
#define KV_STAGE_BYTES (FKEYS * KPAD * 2)     // 17408
#define FSMEM_BYTES (4 * KV_STAGE_BYTES)      // 69632: K0 K1 V0 V1

__global__ __launch_bounds__(128, 3) void flash_kernel(const __half* __restrict__ Q,
                                                       const __half* __restrict__ Kg,
                                                       const __half* __restrict__ Vg,
                                                       __half* __restrict__ O) {
    extern __shared__ char fsm[];
    __half* Ksm = (__half*)fsm;
    __half* Vsm = (__half*)(fsm + 2 * KV_STAGE_BYTES);
    const uint32_t uS = smem_u32(fsm);

    const int tid = threadIdx.x;
    const int warp = tid >> 5, lane = tid & 31;
    const int r = lane >> 2, cq = lane & 3;
    const int q0 = blockIdx.x * 64;
    const int h = blockIdx.y, b = blockIdx.z;
    const size_t head_off = (size_t)b * SEQ * DIM + (size_t)h * HDIM;

    const int ld_row = tid >> 4;           // 0..7  (+8*i)
    const int ld_ch  = tid & 15;           // 16B chunk within row

#define KV_LOAD_STAGE(st, kstart_)                                                  \
    do {                                                                            \
        const __half* Kp = Kg + head_off + (size_t)(kstart_) * DIM;                 \
        const __half* Vp = Vg + head_off + (size_t)(kstart_) * DIM;                 \
        __half* kd = Ksm + (st) * (KV_STAGE_BYTES / 2);                             \
        __half* vd = Vsm + (st) * (KV_STAGE_BYTES / 2);                             \
        _Pragma("unroll")                                                           \
        for (int i = 0; i < 8; i++) {                                               \
            int row = ld_row + i * 8;                                               \
            cp16(kd + row * KPAD + ld_ch * 8, Kp + (size_t)row * DIM + ld_ch * 8);  \
            cp16(vd + row * KPAD + ld_ch * 8, Vp + (size_t)row * DIM + ld_ch * 8);  \
        }                                                                           \
    } while (0)

    // ---- Q fragments: 8 k16-chunks x 4 regs ----
    const __half* Qp = Q + head_off + (size_t)(q0 + warp * 16) * DIM;
    uint32_t aQ[8][4];
#pragma unroll
    for (int kc = 0; kc < 8; kc++) {
        aQ[kc][0] = *(const uint32_t*)(Qp + (size_t)r * DIM + kc * 16 + 2 * cq);
        aQ[kc][1] = *(const uint32_t*)(Qp + (size_t)(r + 8) * DIM + kc * 16 + 2 * cq);
        aQ[kc][2] = *(const uint32_t*)(Qp + (size_t)r * DIM + kc * 16 + 8 + 2 * cq);
        aQ[kc][3] = *(const uint32_t*)(Qp + (size_t)(r + 8) * DIM + kc * 16 + 8 + 2 * cq);
    }

    float o[16][4];
#pragma unroll
    for (int i = 0; i < 16; i++)
#pragma unroll
        for (int j = 0; j < 4; j++) o[i][j] = 0.f;
    float m0 = -1e30f, m1 = -1e30f, l0 = 0.f, l1 = 0.f;

    const int nkb = blockIdx.x + 1;        // causal: 64-key blocks up to q0+63

    KV_LOAD_STAGE(0, 0);
    asm volatile("cp.async.commit_group;");

    for (int kb = 0; kb < nkb; kb++) {
        const int kstart = kb * 64;
        const int st = kb & 1;

        __syncthreads();
        if (kb + 1 < nkb) KV_LOAD_STAGE((kb + 1) & 1, kstart + 64);
        asm volatile("cp.async.commit_group;");
        asm volatile("cp.async.wait_group 1;");   // stage kb resident
        __syncthreads();

        const uint32_t kBase = uS + st * KV_STAGE_BYTES;
        const uint32_t vBase = uS + 2 * KV_STAGE_BYTES + st * KV_STAGE_BYTES;

        // ---- S = Q K^T (16 rows x 64 keys per warp) ----
        float s[8][4];
#pragma unroll
        for (int nt = 0; nt < 8; nt++)
#pragma unroll
            for (int j = 0; j < 4; j++) s[nt][j] = 0.f;
#pragma unroll
        for (int kc = 0; kc < 8; kc++) {
            uint32_t bf[8][2];
#pragma unroll
            for (int g = 0; g < 4; g++) {
                int row = g * 16 + (lane & 7) + ((lane >> 4) << 3);
                int ch = kc * 2 + ((lane >> 3) & 1);
                uint32_t addr = kBase + (uint32_t)(row * (KPAD * 2) + ch * 16);
                LDSM_X4(bf[2 * g][0], bf[2 * g][1], bf[2 * g + 1][0], bf[2 * g + 1][1], addr);
            }
#pragma unroll
            for (int nt = 0; nt < 8; nt++) mma_f16(s[nt], aQ[kc], bf[nt]);
        }

        const float scale = 0.08838834764831843f;  // 1/sqrt(128)
        const int qrow0 = q0 + warp * 16 + r;
        const bool need_mask = (kstart + 63 > q0 + warp * 16);   // only final block
#pragma unroll
        for (int nt = 0; nt < 8; nt++) {
#pragma unroll
            for (int u = 0; u < 2; u++) {
                int key = kstart + nt * 8 + 2 * cq + u;
                s[nt][u] *= scale;
                s[nt][2 + u] *= scale;
                if (need_mask) {
                    if (key > qrow0) s[nt][u] = -1e30f;
                    if (key > qrow0 + 8) s[nt][2 + u] = -1e30f;
                }
            }
        }

        // ---- online softmax ----
        float mx0 = -1e30f, mx1 = -1e30f;
#pragma unroll
        for (int nt = 0; nt < 8; nt++) {
            mx0 = fmaxf(mx0, fmaxf(s[nt][0], s[nt][1]));
            mx1 = fmaxf(mx1, fmaxf(s[nt][2], s[nt][3]));
        }
        mx0 = fmaxf(mx0, __shfl_xor_sync(0xffffffffu, mx0, 1));
        mx0 = fmaxf(mx0, __shfl_xor_sync(0xffffffffu, mx0, 2));
        mx1 = fmaxf(mx1, __shfl_xor_sync(0xffffffffu, mx1, 1));
        mx1 = fmaxf(mx1, __shfl_xor_sync(0xffffffffu, mx1, 2));
        float mn0 = fmaxf(m0, mx0), mn1 = fmaxf(m1, mx1);
        float al0 = __expf(m0 - mn0), al1 = __expf(m1 - mn1);
        float sum0 = 0.f, sum1 = 0.f;
#pragma unroll
        for (int nt = 0; nt < 8; nt++) {
            s[nt][0] = __expf(s[nt][0] - mn0);
            s[nt][1] = __expf(s[nt][1] - mn0);
            s[nt][2] = __expf(s[nt][2] - mn1);
            s[nt][3] = __expf(s[nt][3] - mn1);
            sum0 += s[nt][0] + s[nt][1];
            sum1 += s[nt][2] + s[nt][3];
        }
        sum0 += __shfl_xor_sync(0xffffffffu, sum0, 1);
        sum0 += __shfl_xor_sync(0xffffffffu, sum0, 2);
        sum1 += __shfl_xor_sync(0xffffffffu, sum1, 1);
        sum1 += __shfl_xor_sync(0xffffffffu, sum1, 2);
        l0 = l0 * al0 + sum0;
        l1 = l1 * al1 + sum1;
        m0 = mn0;
        m1 = mn1;
#pragma unroll
        for (int nt = 0; nt < 16; nt++) {
            o[nt][0] *= al0;
            o[nt][1] *= al0;
            o[nt][2] *= al1;
            o[nt][3] *= al1;
        }

        // ---- O += P V : P fragments packed straight from S accumulators ----
#pragma unroll
        for (int g = 0; g < 4; g++) {
            uint32_t aP[4];
            aP[0] = packh2(s[2 * g][0], s[2 * g][1]);
            aP[1] = packh2(s[2 * g][2], s[2 * g][3]);
            aP[2] = packh2(s[2 * g + 1][0], s[2 * g + 1][1]);
            aP[3] = packh2(s[2 * g + 1][2], s[2 * g + 1][3]);
#pragma unroll
            for (int p = 0; p < 8; p++) {   // pairs of d-tiles
                uint32_t bv[2][2];
                int row = g * 16 + (lane & 7) + (((lane >> 3) & 1) << 3);
                int ch = 2 * p + (lane >> 4);
                uint32_t addr = vBase + (uint32_t)(row * (KPAD * 2) + ch * 16);
                LDSM_X4_T(bv[0][0], bv[0][1], bv[1][0], bv[1][1], addr);
                mma_f16(o[2 * p], aP, bv[0]);
                mma_f16(o[2 * p + 1], aP, bv[1]);
            }
        }
    }
#undef KV_LOAD_STAGE

    const float inv0 = 1.f / l0, inv1 = 1.f / l1;
    __half* Op = O + head_off + (size_t)(q0 + warp * 16) * DIM;
#pragma unroll
    for (int nt = 0; nt < 16; nt++) {
        int col = nt * 8 + 2 * cq;
        store_pair(Op + (size_t)r * DIM + col, o[nt][0] * inv0, o[nt][1] * inv0);
        store_pair(Op + (size_t)(r + 8) * DIM + col, o[nt][2] * inv1, o[nt][3] * inv1);
    }
}

// ---------------------------------------------------------------------------
extern "C" void kernel_launch(void* const* d_in, const int* in_sizes, int n_in,
                              void* d_out, int out_size) {
    const float* x  = (const float*)d_in[0];
    const float* Wq = (const float*)d_in[1];
    const float* Wk = (const float*)d_in[2];
    const float* Wv = (const float*)d_in[3];
    const float* Wo = (const float*)d_in[4];
    float* out = (float*)d_out;

    __half *qp, *kp, *vp, *ap, *xr, *wqr, *wkr, *wvr, *wor;
    cudaGetSymbolAddress((void**)&qp, g_q);
    cudaGetSymbolAddress((void**)&kp, g_k);
    cudaGetSymbolAddress((void**)&vp, g_v);
    cudaGetSymbolAddress((void**)&ap, g_attn);
    cudaGetSymbolAddress((void**)&xr, g_xr);
    cudaGetSymbolAddress((void**)&wqr, g_wqr);
    cudaGetSymbolAddress((void**)&wkr, g_wkr);
    cudaGetSymbolAddress((void**)&wvr, g_wvr);
    cudaGetSymbolAddress((void**)&wor, g_wor);

    cudaFuncSetAttribute(gemm_qkv_kernel, cudaFuncAttributeMaxDynamicSharedMemorySize, GSMEM_BYTES);
    cudaFuncSetAttribute(gemm_out_kernel, cudaFuncAttributeMaxDynamicSharedMemorySize, GSMEM_BYTES);
    cudaFuncSetAttribute(flash_kernel, cudaFuncAttributeMaxDynamicSharedMemorySize, FSMEM_BYTES);

    // One fused conversion launch: z=0 covers x (8192 blocks), z=1..4 weights (4096)
    convert_all_kernel<<<dim3(MROWS * DIM / 4 / 256, 1, 5), 256>>>(
        x, Wq, Wk, Wv, Wo, xr, wqr, wkr, wvr, wor);

    dim3 gqkv(DIM / GBN, MROWS / GBM, 3);  // (16, 32, 3)
    gemm_qkv_kernel<<<gqkv, GTHREADS, GSMEM_BYTES>>>(xr, wqr, wkr, wvr, qp, kp, vp);

    const int rope_threads = BATCH * SEQ * NHEAD * 64;
    rope_kernel<<<rope_threads / 256, 256>>>(qp, kp);

    flash_kernel<<<dim3(SEQ / 64, NHEAD, BATCH), 128, FSMEM_BYTES>>>(qp, kp, vp, ap);

    gemm_out_kernel<<<dim3(DIM / GBN, MROWS / GBM), GTHREADS, GSMEM_BYTES>>>(ap, wor, out);
}

// round 14
// speedup vs baseline: 1.2005x; 1.0280x over previous
#include <cuda_runtime.h>
#include <cuda_fp16.h>
#include <cstdint>

#define DIM   2048
#define NHEAD 16
#define HDIM  128
#define BATCH 2
#define SEQ   2048
#define MROWS (BATCH*SEQ)   // 4096

// ---- fp16 GEMM tile config ----
#define GBM 128
#define GBN 128
#define GBK 64                         // 64 halfs = 128 bytes = one swizzle row
#define GSTAGES 3
#define STAGE_T_BYTES (128 * 128)      // one operand tile per stage: 16384 B
#define GSMEM_BYTES (GSTAGES * 2 * STAGE_T_BYTES)   // 98304
#define GTHREADS 128                   // 4 warps, 2x2, warp tile 64x64

#define SW128(o) ((o) ^ ((((uint32_t)(o)) >> 3) & 0x70u))

// Scratch (allocation-free rule: __device__ globals)
__device__ __half g_q[(size_t)MROWS * DIM];
__device__ __half g_k[(size_t)MROWS * DIM];
__device__ __half g_v[(size_t)MROWS * DIM];
__device__ __half g_attn[(size_t)MROWS * DIM];
__device__ __half g_xr[(size_t)MROWS * DIM];
__device__ __half g_wqr[(size_t)DIM * DIM];
__device__ __half g_wkr[(size_t)DIM * DIM];
__device__ __half g_wvr[(size_t)DIM * DIM];
__device__ __half g_wor[(size_t)DIM * DIM];

// ---------------------------------------------------------------------------
// PTX helpers
// ---------------------------------------------------------------------------
__device__ __forceinline__ void mma_f16(float c[4], const uint32_t a[4], const uint32_t b[2]) {
    asm volatile(
        "mma.sync.aligned.m16n8k16.row.col.f32.f16.f16.f32 "
        "{%0,%1,%2,%3}, {%4,%5,%6,%7}, {%8,%9}, {%0,%1,%2,%3};\n"
        : "+f"(c[0]), "+f"(c[1]), "+f"(c[2]), "+f"(c[3])
        : "r"(a[0]), "r"(a[1]), "r"(a[2]), "r"(a[3]), "r"(b[0]), "r"(b[1]));
}

#define LDSM_X4(r0, r1, r2, r3, addr)                                       \
    asm volatile("ldmatrix.sync.aligned.m8n8.x4.shared.b16 {%0,%1,%2,%3}, [%4];" \
                 : "=r"(r0), "=r"(r1), "=r"(r2), "=r"(r3) : "r"(addr))

#define LDSM_X4_T(r0, r1, r2, r3, addr)                                     \
    asm volatile("ldmatrix.sync.aligned.m8n8.x4.trans.shared.b16 {%0,%1,%2,%3}, [%4];" \
                 : "=r"(r0), "=r"(r1), "=r"(r2), "=r"(r3) : "r"(addr))

__device__ __forceinline__ void cp16(void* dst, const void* src) {
    uint32_t s = (uint32_t)__cvta_generic_to_shared(dst);
    asm volatile("cp.async.cg.shared.global [%0], [%1], 16;" :: "r"(s), "l"(src));
}

__device__ __forceinline__ uint32_t smem_u32(const void* p) {
    return (uint32_t)__cvta_generic_to_shared(p);
}

__device__ __forceinline__ uint32_t packh2(float a, float b) {
    __half2 h = __floats2half2_rn(a, b);
    return *(uint32_t*)&h;
}

__device__ __forceinline__ void store_pair(__half* p, float a, float b) {
    *(uint32_t*)p = packh2(a, b);
}
__device__ __forceinline__ void store_pair(float* p, float a, float b) {
    *(float2*)p = make_float2(a, b);
}

// ---------------------------------------------------------------------------
// Fused f32 -> f16 conversion: grid.z selects tensor (0=x, 1..4=weights)
// ---------------------------------------------------------------------------
__global__ void convert_all_kernel(const float* __restrict__ x,
                                   const float* __restrict__ wq, const float* __restrict__ wk,
                                   const float* __restrict__ wv, const float* __restrict__ wo,
                                   __half* __restrict__ xr,
                                   __half* __restrict__ wqr, __half* __restrict__ wkr,
                                   __half* __restrict__ wvr, __half* __restrict__ wor) {
    const int z = blockIdx.z;
    const int nw4 = DIM * DIM / 4;
    if (z > 0 && blockIdx.x >= (unsigned)(nw4 / 256)) return;
    int t = blockIdx.x * 256 + threadIdx.x;
    const float* in;
    __half* out;
    switch (z) {
        case 0: in = x;  out = xr;  break;
        case 1: in = wq; out = wqr; break;
        case 2: in = wk; out = wkr; break;
        case 3: in = wv; out = wvr; break;
        default: in = wo; out = wor; break;
    }
    float4 v = ((const float4*)in)[t];
    ((uint2*)out)[t] = make_uint2(packh2(v.x, v.y), packh2(v.z, v.w));
}

// ---------------------------------------------------------------------------
// fp16 TN GEMM: C[m,n] = sum_k A[m,k]*B[n,k], f32 accumulate.
// CTA 128x128, BK=64 halfs, 4 warps (2x2, warp tile 64x64), 3-stage cp.async,
// SW128-swizzled smem, ldmatrix fragment loads. 64x64 warp tile halves the
// per-CTA A-fragment smem re-reads vs 64x32 (smem-BW was the bound).
// ---------------------------------------------------------------------------
template <typename OutT>
__device__ __forceinline__ void gemm_fp16_body(const __half* __restrict__ A,
                                               const __half* __restrict__ B,
                                               OutT* __restrict__ C,
                                               char* smem) {
    const int K = DIM, N = DIM;
    const int tid = threadIdx.x;
    const int warp = tid >> 5, lane = tid & 31;
    const int m0 = blockIdx.y * GBM, n0 = blockIdx.x * GBN;
    const int wm = warp >> 1, wn = warp & 1;      // 2x2 warps -> warp tile 64x64
    const int r = lane >> 2, cq = lane & 3;

    char* As = smem;
    char* Bs = smem + GSTAGES * STAGE_T_BYTES;
    const uint32_t uA = smem_u32(As);
    const uint32_t uB = smem_u32(Bs);

    float acc[4][8][4];
#pragma unroll
    for (int mt = 0; mt < 4; mt++)
#pragma unroll
        for (int nf = 0; nf < 8; nf++)
#pragma unroll
            for (int q = 0; q < 4; q++) acc[mt][nf][q] = 0.f;

    // 1024 chunks per operand tile, 128 threads -> 8 chunks each per operand
#define G_LOAD_STAGE(slot, kt)                                                     \
    do {                                                                           \
        const __half* Ag = A + (size_t)m0 * K + (size_t)(kt) * GBK;                \
        const __half* Bg = B + (size_t)n0 * K + (size_t)(kt) * GBK;                \
        _Pragma("unroll")                                                          \
        for (int i = 0; i < 8; i++) {                                              \
            int c = tid + i * GTHREADS;                                            \
            int row = c >> 3, ch = c & 7;                                          \
            uint32_t sw = SW128((uint32_t)(row * 128 + ch * 16));                  \
            cp16(As + (slot) * STAGE_T_BYTES + sw, Ag + (size_t)row * K + ch * 8); \
            cp16(Bs + (slot) * STAGE_T_BYTES + sw, Bg + (size_t)row * K + ch * 8); \
        }                                                                          \
    } while (0)

    G_LOAD_STAGE(0, 0);
    asm volatile("cp.async.commit_group;");
    G_LOAD_STAGE(1, 1);
    asm volatile("cp.async.commit_group;");

    const int KT = K / GBK;  // 32
    for (int kt = 0; kt < KT; kt++) {
        asm volatile("cp.async.wait_group 1;");
        __syncthreads();
        int pf = kt + GSTAGES - 1;
        if (pf < KT) G_LOAD_STAGE(pf % GSTAGES, pf);
        asm volatile("cp.async.commit_group;");

        const uint32_t aBase = uA + (kt % GSTAGES) * STAGE_T_BYTES;
        const uint32_t bBase = uB + (kt % GSTAGES) * STAGE_T_BYTES;

#pragma unroll
        for (int kk = 0; kk < 4; kk++) {          // 4 x k16 per stage
            const int c0 = kk * 2;
            uint32_t af[4][4], bf[8][2];
#pragma unroll
            for (int mt = 0; mt < 4; mt++) {
                int row = wm * 64 + mt * 16 + (lane & 15);
                int ch = c0 + (lane >> 4);
                uint32_t addr = aBase + SW128((uint32_t)(row * 128 + ch * 16));
                LDSM_X4(af[mt][0], af[mt][1], af[mt][2], af[mt][3], addr);
            }
#pragma unroll
            for (int g = 0; g < 4; g++) {
                int row = wn * 64 + g * 16 + (lane & 7) + ((lane >> 4) << 3);
                int ch = c0 + ((lane >> 3) & 1);
                uint32_t addr = bBase + SW128((uint32_t)(row * 128 + ch * 16));
                LDSM_X4(bf[2 * g][0], bf[2 * g][1], bf[2 * g + 1][0], bf[2 * g + 1][1], addr);
            }
#pragma unroll
            for (int mt = 0; mt < 4; mt++)
#pragma unroll
                for (int nf = 0; nf < 8; nf++) mma_f16(acc[mt][nf], af[mt], bf[nf]);
        }
        // no bottom __syncthreads — top-of-iteration barrier provides the ordering
    }
#undef G_LOAD_STAGE

#pragma unroll
    for (int mt = 0; mt < 4; mt++) {
        int row0 = m0 + wm * 64 + mt * 16 + r;
#pragma unroll
        for (int nf = 0; nf < 8; nf++) {
            int col = n0 + wn * 64 + nf * 8 + 2 * cq;
            store_pair(C + (size_t)row0 * N + col, acc[mt][nf][0], acc[mt][nf][1]);
            store_pair(C + (size_t)(row0 + 8) * N + col, acc[mt][nf][2], acc[mt][nf][3]);
        }
    }
}

__global__ __launch_bounds__(GTHREADS, 2) void gemm_qkv_kernel(
    const __half* __restrict__ x,
    const __half* __restrict__ wq, const __half* __restrict__ wk, const __half* __restrict__ wv,
    __half* __restrict__ q, __half* __restrict__ k, __half* __restrict__ v) {
    extern __shared__ char smem[];
    const __half* B = (blockIdx.z == 0) ? wq : (blockIdx.z == 1) ? wk : wv;
    __half* C       = (blockIdx.z == 0) ? q  : (blockIdx.z == 1) ? k  : v;
    gemm_fp16_body<__half>(x, B, C, smem);
}

__global__ __launch_bounds__(GTHREADS, 2) void gemm_out_kernel(const __half* __restrict__ A,
                                                               const __half* __restrict__ B,
                                                               float* __restrict__ C) {
    extern __shared__ char smem[];
    gemm_fp16_body<float>(A, B, C, smem);
}

// ---------------------------------------------------------------------------
// RoPE (non-interleaved / chunk-half), in-place on fp16 Q and K.
// ---------------------------------------------------------------------------
__global__ void rope_kernel(__half* __restrict__ q, __half* __restrict__ k) {
    int t = blockIdx.x * blockDim.x + threadIdx.x;
    const int total = BATCH * SEQ * NHEAD * 64;
    if (t >= total) return;
    int j = t & 63;
    int h = (t >> 6) & (NHEAD - 1);
    int s = (t >> 10) & (SEQ - 1);
    int b = t >> 21;
    size_t off = ((size_t)(b * SEQ + s)) * DIM + h * HDIM + j;
    float inv = powf(10000.0f, -(float)(2 * j) * (1.0f / 128.0f));
    float ph = (float)s * inv;
    float sn, cs;
    sincosf(ph, &sn, &cs);
    float q1 = __half2float(q[off]), q2 = __half2float(q[off + 64]);
    q[off]      = __float2half_rn(q1 * cs - q2 * sn);
    q[off + 64] = __float2half_rn(q1 * sn + q2 * cs);
    float k1 = __half2float(k[off]), k2 = __half2float(k[off + 64]);
    k[off]      = __float2half_rn(k1 * cs - k2 * sn);
    k[off + 64] = __float2half_rn(k1 * sn + k2 * cs);
}

// ---------------------------------------------------------------------------
// Causal flash attention, fp16 mma. Grid: (S/64, H, B), 128 threads
// (4 warps x 16 q-rows). 64-key KV blocks, 2-stage cp.async double buffer
// (dynamic smem, 68 KB).
// ---------------------------------------------------------------------------
#define KPAD 136                              // padded row stride in halfs
#define FKEYS 64
#define KV_STAGE_BYTES (FKEYS * KPAD * 2)     // 17408
#define FSMEM_BYTES (4 * KV_STAGE_BYTES)      // 69632: K0 K1 V0 V1

__global__ __launch_bounds__(128, 3) void flash_kernel(const __half* __restrict__ Q,
                                                       const __half* __restrict__ Kg,
                                                       const __half* __restrict__ Vg,
                                                       __half* __restrict__ O) {
    extern __shared__ char fsm[];
    __half* Ksm = (__half*)fsm;
    __half* Vsm = (__half*)(fsm + 2 * KV_STAGE_BYTES);
    const uint32_t uS = smem_u32(fsm);

    const int tid = threadIdx.x;
    const int warp = tid >> 5, lane = tid & 31;
    const int r = lane >> 2, cq = lane & 3;
    const int q0 = blockIdx.x * 64;
    const int h = blockIdx.y, b = blockIdx.z;
    const size_t head_off = (size_t)b * SEQ * DIM + (size_t)h * HDIM;

    const int ld_row = tid >> 4;           // 0..7  (+8*i)
    const int ld_ch  = tid & 15;           // 16B chunk within row

#define KV_LOAD_STAGE(st, kstart_)                                                  \
    do {                                                                            \
        const __half* Kp = Kg + head_off + (size_t)(kstart_) * DIM;                 \
        const __half* Vp = Vg + head_off + (size_t)(kstart_) * DIM;                 \
        __half* kd = Ksm + (st) * (KV_STAGE_BYTES / 2);                             \
        __half* vd = Vsm + (st) * (KV_STAGE_BYTES / 2);                             \
        _Pragma("unroll")                                                           \
        for (int i = 0; i < 8; i++) {                                               \
            int row = ld_row + i * 8;                                               \
            cp16(kd + row * KPAD + ld_ch * 8, Kp + (size_t)row * DIM + ld_ch * 8);  \
            cp16(vd + row * KPAD + ld_ch * 8, Vp + (size_t)row * DIM + ld_ch * 8);  \
        }                                                                           \
    } while (0)

    // ---- Q fragments: 8 k16-chunks x 4 regs ----
    const __half* Qp = Q + head_off + (size_t)(q0 + warp * 16) * DIM;
    uint32_t aQ[8][4];
#pragma unroll
    for (int kc = 0; kc < 8; kc++) {
        aQ[kc][0] = *(const uint32_t*)(Qp + (size_t)r * DIM + kc * 16 + 2 * cq);
        aQ[kc][1] = *(const uint32_t*)(Qp + (size_t)(r + 8) * DIM + kc * 16 + 2 * cq);
        aQ[kc][2] = *(const uint32_t*)(Qp + (size_t)r * DIM + kc * 16 + 8 + 2 * cq);
        aQ[kc][3] = *(const uint32_t*)(Qp + (size_t)(r + 8) * DIM + kc * 16 + 8 + 2 * cq);
    }

    float o[16][4];
#pragma unroll
    for (int i = 0; i < 16; i++)
#pragma unroll
        for (int j = 0; j < 4; j++) o[i][j] = 0.f;
    float m0 = -1e30f, m1 = -1e30f, l0 = 0.f, l1 = 0.f;

    const int nkb = blockIdx.x + 1;        // causal: 64-key blocks up to q0+63

    KV_LOAD_STAGE(0, 0);
    asm volatile("cp.async.commit_group;");

    for (int kb = 0; kb < nkb; kb++) {
        const int kstart = kb * 64;
        const int st = kb & 1;

        __syncthreads();
        if (kb + 1 < nkb) KV_LOAD_STAGE((kb + 1) & 1, kstart + 64);
        asm volatile("cp.async.commit_group;");
        asm volatile("cp.async.wait_group 1;");   // stage kb resident
        __syncthreads();

        const uint32_t kBase = uS + st * KV_STAGE_BYTES;
        const uint32_t vBase = uS + 2 * KV_STAGE_BYTES + st * KV_STAGE_BYTES;

        // ---- S = Q K^T (16 rows x 64 keys per warp) ----
        float s[8][4];
#pragma unroll
        for (int nt = 0; nt < 8; nt++)
#pragma unroll
            for (int j = 0; j < 4; j++) s[nt][j] = 0.f;
#pragma unroll
        for (int kc = 0; kc < 8; kc++) {
            uint32_t bf[8][2];
#pragma unroll
            for (int g = 0; g < 4; g++) {
                int row = g * 16 + (lane & 7) + ((lane >> 4) << 3);
                int ch = kc * 2 + ((lane >> 3) & 1);
                uint32_t addr = kBase + (uint32_t)(row * (KPAD * 2) + ch * 16);
                LDSM_X4(bf[2 * g][0], bf[2 * g][1], bf[2 * g + 1][0], bf[2 * g + 1][1], addr);
            }
#pragma unroll
            for (int nt = 0; nt < 8; nt++) mma_f16(s[nt], aQ[kc], bf[nt]);
        }

        const float scale = 0.08838834764831843f;  // 1/sqrt(128)
        const int qrow0 = q0 + warp * 16 + r;
        const bool need_mask = (kstart + 63 > q0 + warp * 16);   // only final block
#pragma unroll
        for (int nt = 0; nt < 8; nt++) {
#pragma unroll
            for (int u = 0; u < 2; u++) {
                int key = kstart + nt * 8 + 2 * cq + u;
                s[nt][u] *= scale;
                s[nt][2 + u] *= scale;
                if (need_mask) {
                    if (key > qrow0) s[nt][u] = -1e30f;
                    if (key > qrow0 + 8) s[nt][2 + u] = -1e30f;
                }
            }
        }

        // ---- online softmax ----
        float mx0 = -1e30f, mx1 = -1e30f;
#pragma unroll
        for (int nt = 0; nt < 8; nt++) {
            mx0 = fmaxf(mx0, fmaxf(s[nt][0], s[nt][1]));
            mx1 = fmaxf(mx1, fmaxf(s[nt][2], s[nt][3]));
        }
        mx0 = fmaxf(mx0, __shfl_xor_sync(0xffffffffu, mx0, 1));
        mx0 = fmaxf(mx0, __shfl_xor_sync(0xffffffffu, mx0, 2));
        mx1 = fmaxf(mx1, __shfl_xor_sync(0xffffffffu, mx1, 1));
        mx1 = fmaxf(mx1, __shfl_xor_sync(0xffffffffu, mx1, 2));
        float mn0 = fmaxf(m0, mx0), mn1 = fmaxf(m1, mx1);
        float al0 = __expf(m0 - mn0), al1 = __expf(m1 - mn1);
        float sum0 = 0.f, sum1 = 0.f;
#pragma unroll
        for (int nt = 0; nt < 8; nt++) {
            s[nt][0] = __expf(s[nt][0] - mn0);
            s[nt][1] = __expf(s[nt][1] - mn0);
            s[nt][2] = __expf(s[nt][2] - mn1);
            s[nt][3] = __expf(s[nt][3] - mn1);
            sum0 += s[nt][0] + s[nt][1];
            sum1 += s[nt][2] + s[nt][3];
        }
        sum0 += __shfl_xor_sync(0xffffffffu, sum0, 1);
        sum0 += __shfl_xor_sync(0xffffffffu, sum0, 2);
        sum1 += __shfl_xor_sync(0xffffffffu, sum1, 1);
        sum1 += __shfl_xor_sync(0xffffffffu, sum1, 2);
        l0 = l0 * al0 + sum0;
        l1 = l1 * al1 + sum1;
        m0 = mn0;
        m1 = mn1;
#pragma unroll
        for (int nt = 0; nt < 16; nt++) {
            o[nt][0] *= al0;
            o[nt][1] *= al0;
            o[nt][2] *= al1;
            o[nt][3] *= al1;
        }

        // ---- O += P V : P fragments packed straight from S accumulators ----
#pragma unroll
        for (int g = 0; g < 4; g++) {
            uint32_t aP[4];
            aP[0] = packh2(s[2 * g][0], s[2 * g][1]);
            aP[1] = packh2(s[2 * g][2], s[2 * g][3]);
            aP[2] = packh2(s[2 * g + 1][0], s[2 * g + 1][1]);
            aP[3] = packh2(s[2 * g + 1][2], s[2 * g + 1][3]);
#pragma unroll
            for (int p = 0; p < 8; p++) {   // pairs of d-tiles
                uint32_t bv[2][2];
                int row = g * 16 + (lane & 7) + (((lane >> 3) & 1) << 3);
                int ch = 2 * p + (lane >> 4);
                uint32_t addr = vBase + (uint32_t)(row * (KPAD * 2) + ch * 16);
                LDSM_X4_T(bv[0][0], bv[0][1], bv[1][0], bv[1][1], addr);
                mma_f16(o[2 * p], aP, bv[0]);
                mma_f16(o[2 * p + 1], aP, bv[1]);
            }
        }
    }
#undef KV_LOAD_STAGE

    const float inv0 = 1.f / l0, inv1 = 1.f / l1;
    __half* Op = O + head_off + (size_t)(q0 + warp * 16) * DIM;
#pragma unroll
    for (int nt = 0; nt < 16; nt++) {
        int col = nt * 8 + 2 * cq;
        store_pair(Op + (size_t)r * DIM + col, o[nt][0] * inv0, o[nt][1] * inv0);
        store_pair(Op + (size_t)(r + 8) * DIM + col, o[nt][2] * inv1, o[nt][3] * inv1);
    }
}

// ---------------------------------------------------------------------------
extern "C" void kernel_launch(void* const* d_in, const int* in_sizes, int n_in,
                              void* d_out, int out_size) {
    const float* x  = (const float*)d_in[0];
    const float* Wq = (const float*)d_in[1];
    const float* Wk = (const float*)d_in[2];
    const float* Wv = (const float*)d_in[3];
    const float* Wo = (const float*)d_in[4];
    float* out = (float*)d_out;

    __half *qp, *kp, *vp, *ap, *xr, *wqr, *wkr, *wvr, *wor;
    cudaGetSymbolAddress((void**)&qp, g_q);
    cudaGetSymbolAddress((void**)&kp, g_k);
    cudaGetSymbolAddress((void**)&vp, g_v);
    cudaGetSymbolAddress((void**)&ap, g_attn);
    cudaGetSymbolAddress((void**)&xr, g_xr);
    cudaGetSymbolAddress((void**)&wqr, g_wqr);
    cudaGetSymbolAddress((void**)&wkr, g_wkr);
    cudaGetSymbolAddress((void**)&wvr, g_wvr);
    cudaGetSymbolAddress((void**)&wor, g_wor);

    cudaFuncSetAttribute(gemm_qkv_kernel, cudaFuncAttributeMaxDynamicSharedMemorySize, GSMEM_BYTES);
    cudaFuncSetAttribute(gemm_out_kernel, cudaFuncAttributeMaxDynamicSharedMemorySize, GSMEM_BYTES);
    cudaFuncSetAttribute(flash_kernel, cudaFuncAttributeMaxDynamicSharedMemorySize, FSMEM_BYTES);

    // One fused conversion launch: z=0 covers x (8192 blocks), z=1..4 weights (4096)
    convert_all_kernel<<<dim3(MROWS * DIM / 4 / 256, 1, 5), 256>>>(
        x, Wq, Wk, Wv, Wo, xr, wqr, wkr, wvr, wor);

    dim3 gqkv(DIM / GBN, MROWS / GBM, 3);  // (16, 32, 3)
    gemm_qkv_kernel<<<gqkv, GTHREADS, GSMEM_BYTES>>>(xr, wqr, wkr, wvr, qp, kp, vp);

    const int rope_threads = BATCH * SEQ * NHEAD * 64;
    rope_kernel<<<rope_threads / 256, 256>>>(qp, kp);

    flash_kernel<<<dim3(SEQ / 64, NHEAD, BATCH), 128, FSMEM_BYTES>>>(qp, kp, vp, ap);

    gemm_out_kernel<<<dim3(DIM / GBN, MROWS / GBM), GTHREADS, GSMEM_BYTES>>>(ap, wor, out);
}

// round 16
// speedup vs baseline: 1.2110x; 1.0088x over previous
#include <cuda_runtime.h>
#include <cuda_fp16.h>
#include <cstdint>

#define DIM   2048
#define NHEAD 16
#define HDIM  128
#define BATCH 2
#define SEQ   2048
#define MROWS (BATCH*SEQ)   // 4096

// ---- fp16 GEMM tile config ----
#define GBM 128
#define GBN 128
#define GBK 64                         // 64 halfs = 128 bytes = one swizzle row
#define GSTAGES 3
#define STAGE_T_BYTES (128 * 128)      // one operand tile per stage: 16384 B
#define GSMEM_BYTES (GSTAGES * 2 * STAGE_T_BYTES)   // 98304
#define GTHREADS 128                   // 4 warps, 2x2, warp tile 64x64

#define SW128(o) ((o) ^ ((((uint32_t)(o)) >> 3) & 0x70u))

// log2(10000)/64 : inv_freq(j) = 2^(-j * ROPE_C) = 10000^(-2j/128)
#define ROPE_C 0.20762050593046014f

// Scratch (allocation-free rule: __device__ globals)
__device__ __half g_q[(size_t)MROWS * DIM];
__device__ __half g_k[(size_t)MROWS * DIM];
__device__ __half g_v[(size_t)MROWS * DIM];
__device__ __half g_attn[(size_t)MROWS * DIM];
__device__ __half g_xr[(size_t)MROWS * DIM];
__device__ __half g_wqr[(size_t)DIM * DIM];
__device__ __half g_wkr[(size_t)DIM * DIM];
__device__ __half g_wvr[(size_t)DIM * DIM];
__device__ __half g_wor[(size_t)DIM * DIM];

// ---------------------------------------------------------------------------
// PTX helpers
// ---------------------------------------------------------------------------
__device__ __forceinline__ void mma_f16(float c[4], const uint32_t a[4], const uint32_t b[2]) {
    asm volatile(
        "mma.sync.aligned.m16n8k16.row.col.f32.f16.f16.f32 "
        "{%0,%1,%2,%3}, {%4,%5,%6,%7}, {%8,%9}, {%0,%1,%2,%3};\n"
        : "+f"(c[0]), "+f"(c[1]), "+f"(c[2]), "+f"(c[3])
        : "r"(a[0]), "r"(a[1]), "r"(a[2]), "r"(a[3]), "r"(b[0]), "r"(b[1]));
}

#define LDSM_X4(r0, r1, r2, r3, addr)                                       \
    asm volatile("ldmatrix.sync.aligned.m8n8.x4.shared.b16 {%0,%1,%2,%3}, [%4];" \
                 : "=r"(r0), "=r"(r1), "=r"(r2), "=r"(r3) : "r"(addr))

#define LDSM_X4_T(r0, r1, r2, r3, addr)                                     \
    asm volatile("ldmatrix.sync.aligned.m8n8.x4.trans.shared.b16 {%0,%1,%2,%3}, [%4];" \
                 : "=r"(r0), "=r"(r1), "=r"(r2), "=r"(r3) : "r"(addr))

__device__ __forceinline__ void cp16(void* dst, const void* src) {
    uint32_t s = (uint32_t)__cvta_generic_to_shared(dst);
    asm volatile("cp.async.cg.shared.global [%0], [%1], 16;" :: "r"(s), "l"(src));
}

__device__ __forceinline__ uint32_t smem_u32(const void* p) {
    return (uint32_t)__cvta_generic_to_shared(p);
}

__device__ __forceinline__ uint32_t packh2(float a, float b) {
    __half2 h = __floats2half2_rn(a, b);
    return *(uint32_t*)&h;
}

__device__ __forceinline__ void store_pair(__half* p, float a, float b) {
    *(uint32_t*)p = packh2(a, b);
}
__device__ __forceinline__ void store_pair(float* p, float a, float b) {
    *(float2*)p = make_float2(a, b);
}

// ---------------------------------------------------------------------------
// Fused f32 -> f16 conversion: grid.z selects tensor (0=x, 1..4=weights)
// ---------------------------------------------------------------------------
__global__ void convert_all_kernel(const float* __restrict__ x,
                                   const float* __restrict__ wq, const float* __restrict__ wk,
                                   const float* __restrict__ wv, const float* __restrict__ wo,
                                   __half* __restrict__ xr,
                                   __half* __restrict__ wqr, __half* __restrict__ wkr,
                                   __half* __restrict__ wvr, __half* __restrict__ wor) {
    const int z = blockIdx.z;
    const int nw4 = DIM * DIM / 4;
    if (z > 0 && blockIdx.x >= (unsigned)(nw4 / 256)) return;
    int t = blockIdx.x * 256 + threadIdx.x;
    const float* in;
    __half* out;
    switch (z) {
        case 0: in = x;  out = xr;  break;
        case 1: in = wq; out = wqr; break;
        case 2: in = wk; out = wkr; break;
        case 3: in = wv; out = wvr; break;
        default: in = wo; out = wor; break;
    }
    float4 v = ((const float4*)in)[t];
    ((uint2*)out)[t] = make_uint2(packh2(v.x, v.y), packh2(v.z, v.w));
}

// ---------------------------------------------------------------------------
// fp16 TN GEMM: C[m,n] = sum_k A[m,k]*B[n,k], f32 accumulate.
// CTA 128x128, BK=64 halfs, 4 warps (2x2, warp tile 64x64), 3-stage cp.async,
// SW128-swizzled smem, ldmatrix fragment loads.
// ---------------------------------------------------------------------------
template <typename OutT>
__device__ __forceinline__ void gemm_fp16_body(const __half* __restrict__ A,
                                               const __half* __restrict__ B,
                                               OutT* __restrict__ C,
                                               char* smem) {
    const int K = DIM, N = DIM;
    const int tid = threadIdx.x;
    const int warp = tid >> 5, lane = tid & 31;
    const int m0 = blockIdx.y * GBM, n0 = blockIdx.x * GBN;
    const int wm = warp >> 1, wn = warp & 1;      // 2x2 warps -> warp tile 64x64
    const int r = lane >> 2, cq = lane & 3;

    char* As = smem;
    char* Bs = smem + GSTAGES * STAGE_T_BYTES;
    const uint32_t uA = smem_u32(As);
    const uint32_t uB = smem_u32(Bs);

    float acc[4][8][4];
#pragma unroll
    for (int mt = 0; mt < 4; mt++)
#pragma unroll
        for (int nf = 0; nf < 8; nf++)
#pragma unroll
            for (int q = 0; q < 4; q++) acc[mt][nf][q] = 0.f;

    // 1024 chunks per operand tile, 128 threads -> 8 chunks each per operand
#define G_LOAD_STAGE(slot, kt)                                                     \
    do {                                                                           \
        const __half* Ag = A + (size_t)m0 * K + (size_t)(kt) * GBK;                \
        const __half* Bg = B + (size_t)n0 * K + (size_t)(kt) * GBK;                \
        _Pragma("unroll")                                                          \
        for (int i = 0; i < 8; i++) {                                              \
            int c = tid + i * GTHREADS;                                            \
            int row = c >> 3, ch = c & 7;                                          \
            uint32_t sw = SW128((uint32_t)(row * 128 + ch * 16));                  \
            cp16(As + (slot) * STAGE_T_BYTES + sw, Ag + (size_t)row * K + ch * 8); \
            cp16(Bs + (slot) * STAGE_T_BYTES + sw, Bg + (size_t)row * K + ch * 8); \
        }                                                                          \
    } while (0)

    G_LOAD_STAGE(0, 0);
    asm volatile("cp.async.commit_group;");
    G_LOAD_STAGE(1, 1);
    asm volatile("cp.async.commit_group;");

    const int KT = K / GBK;  // 32
    for (int kt = 0; kt < KT; kt++) {
        asm volatile("cp.async.wait_group 1;");
        __syncthreads();
        int pf = kt + GSTAGES - 1;
        if (pf < KT) G_LOAD_STAGE(pf % GSTAGES, pf);
        asm volatile("cp.async.commit_group;");

        const uint32_t aBase = uA + (kt % GSTAGES) * STAGE_T_BYTES;
        const uint32_t bBase = uB + (kt % GSTAGES) * STAGE_T_BYTES;

#pragma unroll
        for (int kk = 0; kk < 4; kk++) {          // 4 x k16 per stage
            const int c0 = kk * 2;
            uint32_t af[4][4], bf[8][2];
#pragma unroll
            for (int mt = 0; mt < 4; mt++) {
                int row = wm * 64 + mt * 16 + (lane & 15);
                int ch = c0 + (lane >> 4);
                uint32_t addr = aBase + SW128((uint32_t)(row * 128 + ch * 16));
                LDSM_X4(af[mt][0], af[mt][1], af[mt][2], af[mt][3], addr);
            }
#pragma unroll
            for (int g = 0; g < 4; g++) {
                int row = wn * 64 + g * 16 + (lane & 7) + ((lane >> 4) << 3);
                int ch = c0 + ((lane >> 3) & 1);
                uint32_t addr = bBase + SW128((uint32_t)(row * 128 + ch * 16));
                LDSM_X4(bf[2 * g][0], bf[2 * g][1], bf[2 * g + 1][0], bf[2 * g + 1][1], addr);
            }
#pragma unroll
            for (int mt = 0; mt < 4; mt++)
#pragma unroll
                for (int nf = 0; nf < 8; nf++) mma_f16(acc[mt][nf], af[mt], bf[nf]);
        }
        // no bottom __syncthreads — top-of-iteration barrier provides the ordering
    }
#undef G_LOAD_STAGE

#pragma unroll
    for (int mt = 0; mt < 4; mt++) {
        int row0 = m0 + wm * 64 + mt * 16 + r;
#pragma unroll
        for (int nf = 0; nf < 8; nf++) {
            int col = n0 + wn * 64 + nf * 8 + 2 * cq;
            store_pair(C + (size_t)row0 * N + col, acc[mt][nf][0], acc[mt][nf][1]);
            store_pair(C + (size_t)(row0 + 8) * N + col, acc[mt][nf][2], acc[mt][nf][3]);
        }
    }
}

__global__ __launch_bounds__(GTHREADS, 2) void gemm_qkv_kernel(
    const __half* __restrict__ x,
    const __half* __restrict__ wq, const __half* __restrict__ wk, const __half* __restrict__ wv,
    __half* __restrict__ q, __half* __restrict__ k, __half* __restrict__ v) {
    extern __shared__ char smem[];
    const __half* B = (blockIdx.z == 0) ? wq : (blockIdx.z == 1) ? wk : wv;
    __half* C       = (blockIdx.z == 0) ? q  : (blockIdx.z == 1) ? k  : v;
    gemm_fp16_body<__half>(x, B, C, smem);
}

__global__ __launch_bounds__(GTHREADS, 2) void gemm_out_kernel(const __half* __restrict__ A,
                                                               const __half* __restrict__ B,
                                                               float* __restrict__ C) {
    extern __shared__ char smem[];
    gemm_fp16_body<float>(A, B, C, smem);
}

// ---------------------------------------------------------------------------
// RoPE (non-interleaved / chunk-half), in-place on fp16 Q and K.
// exp2f replaces powf: 10000^(-2j/128) == 2^(-j*log2(10000)/64), cheaper MUFU.
// ---------------------------------------------------------------------------
__global__ void rope_kernel(__half* __restrict__ q, __half* __restrict__ k) {
    int t = blockIdx.x * blockDim.x + threadIdx.x;
    const int total = BATCH * SEQ * NHEAD * 64;
    if (t >= total) return;
    int j = t & 63;
    int h = (t >> 6) & (NHEAD - 1);
    int s = (t >> 10) & (SEQ - 1);
    int b = t >> 21;
    size_t off = ((size_t)(b * SEQ + s)) * DIM + h * HDIM + j;
    float inv = exp2f(-(float)j * ROPE_C);
    float ph = (float)s * inv;
    float sn, cs;
    sincosf(ph, &sn, &cs);
    float q1 = __half2float(q[off]), q2 = __half2float(q[off + 64]);
    q[off]      = __float2half_rn(q1 * cs - q2 * sn);
    q[off + 64] = __float2half_rn(q1 * sn + q2 * cs);
    float k1 = __half2float(k[off]), k2 = __half2float(k[off + 64]);
    k[off]      = __float2half_rn(k1 * cs - k2 * sn);
    k[off + 64] = __float2half_rn(k1 * sn + k2 * cs);
}

// ---------------------------------------------------------------------------
// Causal flash attention, fp16 mma. Grid: (S/64, H, B), 128 threads
// (4 warps x 16 q-rows). 64-key KV blocks, 2-stage cp.async double buffer.
// LARGEST-FIRST q-block mapping: qblk = gridDim.x-1-blockIdx.x so the
// longest-chain CTAs (most KV blocks) start in wave 1 — kernel time is
// bounded by their serial chain, not by late starts.
// ---------------------------------------------------------------------------
#define KPAD 136                              // padded row stride in halfs
#define FKEYS 64
#define KV_STAGE_BYTES (FKEYS * KPAD * 2)     // 17408
#define FSMEM_BYTES (4 * KV_STAGE_BYTES)      // 69632: K0 K1 V0 V1

__global__ __launch_bounds__(128, 3) void flash_kernel(const __half* __restrict__ Q,
                                                       const __half* __restrict__ Kg,
                                                       const __half* __restrict__ Vg,
                                                       __half* __restrict__ O) {
    extern __shared__ char fsm[];
    __half* Ksm = (__half*)fsm;
    __half* Vsm = (__half*)(fsm + 2 * KV_STAGE_BYTES);
    const uint32_t uS = smem_u32(fsm);

    const int tid = threadIdx.x;
    const int warp = tid >> 5, lane = tid & 31;
    const int r = lane >> 2, cq = lane & 3;
    const int qblk = gridDim.x - 1 - blockIdx.x;   // largest-first
    const int q0 = qblk * 64;
    const int h = blockIdx.y, b = blockIdx.z;
    const size_t head_off = (size_t)b * SEQ * DIM + (size_t)h * HDIM;

    const int ld_row = tid >> 4;           // 0..7  (+8*i)
    const int ld_ch  = tid & 15;           // 16B chunk within row

#define KV_LOAD_STAGE(st, kstart_)                                                  \
    do {                                                                            \
        const __half* Kp = Kg + head_off + (size_t)(kstart_) * DIM;                 \
        const __half* Vp = Vg + head_off + (size_t)(kstart_) * DIM;                 \
        __half* kd = Ksm + (st) * (KV_STAGE_BYTES / 2);                             \
        __half* vd = Vsm + (st) * (KV_STAGE_BYTES / 2);                             \
        _Pragma("unroll")                                                           \
        for (int i = 0; i < 8; i++) {                                               \
            int row = ld_row + i * 8;                                               \
            cp16(kd + row * KPAD + ld_ch * 8, Kp + (size_t)row * DIM + ld_ch * 8);  \
            cp16(vd + row * KPAD + ld_ch * 8, Vp + (size_t)row * DIM + ld_ch * 8);  \
        }                                                                           \
    } while (0)

    // ---- Q fragments: 8 k16-chunks x 4 regs ----
    const __half* Qp = Q + head_off + (size_t)(q0 + warp * 16) * DIM;
    uint32_t aQ[8][4];
#pragma unroll
    for (int kc = 0; kc < 8; kc++) {
        aQ[kc][0] = *(const uint32_t*)(Qp + (size_t)r * DIM + kc * 16 + 2 * cq);
        aQ[kc][1] = *(const uint32_t*)(Qp + (size_t)(r + 8) * DIM + kc * 16 + 2 * cq);
        aQ[kc][2] = *(const uint32_t*)(Qp + (size_t)r * DIM + kc * 16 + 8 + 2 * cq);
        aQ[kc][3] = *(const uint32_t*)(Qp + (size_t)(r + 8) * DIM + kc * 16 + 8 + 2 * cq);
    }

    float o[16][4];
#pragma unroll
    for (int i = 0; i < 16; i++)
#pragma unroll
        for (int j = 0; j < 4; j++) o[i][j] = 0.f;
    float m0 = -1e30f, m1 = -1e30f, l0 = 0.f, l1 = 0.f;

    const int nkb = qblk + 1;              // causal: 64-key blocks up to q0+63

    KV_LOAD_STAGE(0, 0);
    asm volatile("cp.async.commit_group;");

    for (int kb = 0; kb < nkb; kb++) {
        const int kstart = kb * 64;
        const int st = kb & 1;

        __syncthreads();
        if (kb + 1 < nkb) KV_LOAD_STAGE((kb + 1) & 1, kstart + 64);
        asm volatile("cp.async.commit_group;");
        asm volatile("cp.async.wait_group 1;");   // stage kb resident
        __syncthreads();

        const uint32_t kBase = uS + st * KV_STAGE_BYTES;
        const uint32_t vBase = uS + 2 * KV_STAGE_BYTES + st * KV_STAGE_BYTES;

        // ---- S = Q K^T (16 rows x 64 keys per warp) ----
        float s[8][4];
#pragma unroll
        for (int nt = 0; nt < 8; nt++)
#pragma unroll
            for (int j = 0; j < 4; j++) s[nt][j] = 0.f;
#pragma unroll
        for (int kc = 0; kc < 8; kc++) {
            uint32_t bf[8][2];
#pragma unroll
            for (int g = 0; g < 4; g++) {
                int row = g * 16 + (lane & 7) + ((lane >> 4) << 3);
                int ch = kc * 2 + ((lane >> 3) & 1);
                uint32_t addr = kBase + (uint32_t)(row * (KPAD * 2) + ch * 16);
                LDSM_X4(bf[2 * g][0], bf[2 * g][1], bf[2 * g + 1][0], bf[2 * g + 1][1], addr);
            }
#pragma unroll
            for (int nt = 0; nt < 8; nt++) mma_f16(s[nt], aQ[kc], bf[nt]);
        }

        const float scale = 0.08838834764831843f;  // 1/sqrt(128)
        const int qrow0 = q0 + warp * 16 + r;
        const bool need_mask = (kstart + 63 > q0 + warp * 16);   // only final block
#pragma unroll
        for (int nt = 0; nt < 8; nt++) {
#pragma unroll
            for (int u = 0; u < 2; u++) {
                int key = kstart + nt * 8 + 2 * cq + u;
                s[nt][u] *= scale;
                s[nt][2 + u] *= scale;
                if (need_mask) {
                    if (key > qrow0) s[nt][u] = -1e30f;
                    if (key > qrow0 + 8) s[nt][2 + u] = -1e30f;
                }
            }
        }

        // ---- online softmax ----
        float mx0 = -1e30f, mx1 = -1e30f;
#pragma unroll
        for (int nt = 0; nt < 8; nt++) {
            mx0 = fmaxf(mx0, fmaxf(s[nt][0], s[nt][1]));
            mx1 = fmaxf(mx1, fmaxf(s[nt][2], s[nt][3]));
        }
        mx0 = fmaxf(mx0, __shfl_xor_sync(0xffffffffu, mx0, 1));
        mx0 = fmaxf(mx0, __shfl_xor_sync(0xffffffffu, mx0, 2));
        mx1 = fmaxf(mx1, __shfl_xor_sync(0xffffffffu, mx1, 1));
        mx1 = fmaxf(mx1, __shfl_xor_sync(0xffffffffu, mx1, 2));
        float mn0 = fmaxf(m0, mx0), mn1 = fmaxf(m1, mx1);
        float al0 = __expf(m0 - mn0), al1 = __expf(m1 - mn1);
        float sum0 = 0.f, sum1 = 0.f;
#pragma unroll
        for (int nt = 0; nt < 8; nt++) {
            s[nt][0] = __expf(s[nt][0] - mn0);
            s[nt][1] = __expf(s[nt][1] - mn0);
            s[nt][2] = __expf(s[nt][2] - mn1);
            s[nt][3] = __expf(s[nt][3] - mn1);
            sum0 += s[nt][0] + s[nt][1];
            sum1 += s[nt][2] + s[nt][3];
        }
        sum0 += __shfl_xor_sync(0xffffffffu, sum0, 1);
        sum0 += __shfl_xor_sync(0xffffffffu, sum0, 2);
        sum1 += __shfl_xor_sync(0xffffffffu, sum1, 1);
        sum1 += __shfl_xor_sync(0xffffffffu, sum1, 2);
        l0 = l0 * al0 + sum0;
        l1 = l1 * al1 + sum1;
        m0 = mn0;
        m1 = mn1;
#pragma unroll
        for (int nt = 0; nt < 16; nt++) {
            o[nt][0] *= al0;
            o[nt][1] *= al0;
            o[nt][2] *= al1;
            o[nt][3] *= al1;
        }

        // ---- O += P V : P fragments packed straight from S accumulators ----
#pragma unroll
        for (int g = 0; g < 4; g++) {
            uint32_t aP[4];
            aP[0] = packh2(s[2 * g][0], s[2 * g][1]);
            aP[1] = packh2(s[2 * g][2], s[2 * g][3]);
            aP[2] = packh2(s[2 * g + 1][0], s[2 * g + 1][1]);
            aP[3] = packh2(s[2 * g + 1][2], s[2 * g + 1][3]);
#pragma unroll
            for (int p = 0; p < 8; p++) {   // pairs of d-tiles
                uint32_t bv[2][2];
                int row = g * 16 + (lane & 7) + (((lane >> 3) & 1) << 3);
                int ch = 2 * p + (lane >> 4);
                uint32_t addr = vBase + (uint32_t)(row * (KPAD * 2) + ch * 16);
                LDSM_X4_T(bv[0][0], bv[0][1], bv[1][0], bv[1][1], addr);
                mma_f16(o[2 * p], aP, bv[0]);
                mma_f16(o[2 * p + 1], aP, bv[1]);
            }
        }
    }
#undef KV_LOAD_STAGE

    const float inv0 = 1.f / l0, inv1 = 1.f / l1;
    __half* Op = O + head_off + (size_t)(q0 + warp * 16) * DIM;
#pragma unroll
    for (int nt = 0; nt < 16; nt++) {
        int col = nt * 8 + 2 * cq;
        store_pair(Op + (size_t)r * DIM + col, o[nt][0] * inv0, o[nt][1] * inv0);
        store_pair(Op + (size_t)(r + 8) * DIM + col, o[nt][2] * inv1, o[nt][3] * inv1);
    }
}

// ---------------------------------------------------------------------------
extern "C" void kernel_launch(void* const* d_in, const int* in_sizes, int n_in,
                              void* d_out, int out_size) {
    const float* x  = (const float*)d_in[0];
    const float* Wq = (const float*)d_in[1];
    const float* Wk = (const float*)d_in[2];
    const float* Wv = (const float*)d_in[3];
    const float* Wo = (const float*)d_in[4];
    float* out = (float*)d_out;

    __half *qp, *kp, *vp, *ap, *xr, *wqr, *wkr, *wvr, *wor;
    cudaGetSymbolAddress((void**)&qp, g_q);
    cudaGetSymbolAddress((void**)&kp, g_k);
    cudaGetSymbolAddress((void**)&vp, g_v);
    cudaGetSymbolAddress((void**)&ap, g_attn);
    cudaGetSymbolAddress((void**)&xr, g_xr);
    cudaGetSymbolAddress((void**)&wqr, g_wqr);
    cudaGetSymbolAddress((void**)&wkr, g_wkr);
    cudaGetSymbolAddress((void**)&wvr, g_wvr);
    cudaGetSymbolAddress((void**)&wor, g_wor);

    cudaFuncSetAttribute(gemm_qkv_kernel, cudaFuncAttributeMaxDynamicSharedMemorySize, GSMEM_BYTES);
    cudaFuncSetAttribute(gemm_out_kernel, cudaFuncAttributeMaxDynamicSharedMemorySize, GSMEM_BYTES);
    cudaFuncSetAttribute(flash_kernel, cudaFuncAttributeMaxDynamicSharedMemorySize, FSMEM_BYTES);

    // One fused conversion launch: z=0 covers x (8192 blocks), z=1..4 weights (4096)
    convert_all_kernel<<<dim3(MROWS * DIM / 4 / 256, 1, 5), 256>>>(
        x, Wq, Wk, Wv, Wo, xr, wqr, wkr, wvr, wor);

    dim3 gqkv(DIM / GBN, MROWS / GBM, 3);  // (16, 32, 3)
    gemm_qkv_kernel<<<gqkv, GTHREADS, GSMEM_BYTES>>>(xr, wqr, wkr, wvr, qp, kp, vp);

    const int rope_threads = BATCH * SEQ * NHEAD * 64;
    rope_kernel<<<rope_threads / 256, 256>>>(qp, kp);

    flash_kernel<<<dim3(SEQ / 64, NHEAD, BATCH), 128, FSMEM_BYTES>>>(qp, kp, vp, ap);

    gemm_out_kernel<<<dim3(DIM / GBN, MROWS / GBM), GTHREADS, GSMEM_BYTES>>>(ap, wor, out);
}